// round 4
// baseline (speedup 1.0000x reference)
#include <cuda_runtime.h>
#include <math.h>

#define NNODES 100000
#define CIN    256
#define NHEADS 4
#define DHEAD  64
#define TILE   64
#define NT     ((NNODES + TILE - 1) / TILE)   // 1563
#define BPH    37                              // blocks per head -> 148 blocks
#define XSS    260                             // xs smem row stride (floats)
#define KST    68                              // ks/qs smem row stride (floats)

// ---------------- deterministic scratch (no atomics) ----------------
__device__ float g_part_kvs[BPH][NHEADS * DHEAD * CIN];
__device__ float g_part_kss[BPH][NHEADS * DHEAD];
__device__ float g_part_cs [BPH][CIN];
__device__ float g_kvs   [NHEADS * DHEAD * CIN];
__device__ float g_kssum [NHEADS * DHEAD];
__device__ float g_colsum[CIN];

extern __shared__ float smf[];

// =====================================================================
// Phase A: k-projection + normalize + kv/ks_sum/colsum accumulation
// =====================================================================
__global__ __launch_bounds__(256, 1)
void phaseA_kernel(const float* __restrict__ x,
                   const float* __restrict__ Wk,
                   const float* __restrict__ bk)
{
    const int h   = blockIdx.y;
    const int bx  = blockIdx.x;
    const int tid = threadIdx.x;

    float* xs   = smf;                      // [TILE][XSS]
    float* wt   = xs  + TILE * XSS;         // [CIN][DHEAD]
    float* kv   = wt  + CIN * DHEAD;        // [DHEAD][CIN]
    float* ks   = kv  + DHEAD * CIN;        // [TILE][KST]
    float* bias = ks  + TILE * KST;         // [DHEAD]
    float* kss  = bias + DHEAD;             // [DHEAD]
    float* cs   = kss + DHEAD;              // [CIN]
    float* red  = cs  + CIN;                // [256]
    float* inv  = red + 256;                // [TILE]

    // stage Wk^T: wt[c][m] = Wk[(h*64+m)*256 + c]
    for (int i = tid; i < DHEAD * CIN; i += 256) {
        int c = i & (CIN - 1);
        int m = i >> 8;
        wt[c * DHEAD + m] = Wk[(h * DHEAD + m) * CIN + c];
    }
    for (int i = tid; i < DHEAD * CIN; i += 256) kv[i] = 0.f;
    if (tid < DHEAD) { bias[tid] = bk[h * DHEAD + tid]; kss[tid] = 0.f; }
    if (tid < CIN)   cs[tid] = 0.f;
    __syncthreads();

    // projection mapping: tx8 -> m cols {4tx8..+3} and {4tx8+32..+35}; ty32 -> rows 2ty32, +1
    const int tx8  = tid & 7;
    const int ty32 = tid >> 3;
    const int r0   = 2 * ty32;
    // kv mapping
    const int txk = tid & 15;
    const int tyk = tid >> 4;

    for (int tile = bx; tile < NT; tile += BPH) {
        const int base  = tile * TILE;
        int valid = NNODES - base; if (valid > TILE) valid = TILE;

        // load x tile
        for (int i = tid; i < TILE * 64; i += 256) {
            int n  = i >> 6;
            int c4 = (i & 63) << 2;
            float4 v = make_float4(0.f, 0.f, 0.f, 0.f);
            if (n < valid)
                v = *reinterpret_cast<const float4*>(x + (size_t)(base + n) * CIN + c4);
            *reinterpret_cast<float4*>(xs + n * XSS + c4) = v;
        }
        __syncthreads();

        // ---- projection P[n][m] = sum_c xs[n][c]*wt[c][m]
        // per thread: rows {r0, r0+1}, m cols {4tx8..+3, 4tx8+32..+35}
        {
            float acc[2][8];
            #pragma unroll
            for (int j = 0; j < 2; j++)
                #pragma unroll
                for (int p = 0; p < 8; p++) acc[j][p] = 0.f;

            const float* xr0 = xs + r0 * XSS;
            const float* xr1 = xr0 + XSS;
            const float* wp0 = wt + 4 * tx8;
            #pragma unroll 2
            for (int c0 = 0; c0 < CIN; c0 += 4) {
                float4 av0 = *reinterpret_cast<const float4*>(xr0 + c0);
                float4 av1 = *reinterpret_cast<const float4*>(xr1 + c0);
                float a0[4] = {av0.x, av0.y, av0.z, av0.w};
                float a1[4] = {av1.x, av1.y, av1.z, av1.w};
                #pragma unroll
                for (int u = 0; u < 4; u++) {
                    const float* wc = wp0 + (c0 + u) * DHEAD;
                    float4 blo = *reinterpret_cast<const float4*>(wc);
                    float4 bhi = *reinterpret_cast<const float4*>(wc + 32);
                    acc[0][0] += a0[u] * blo.x; acc[0][1] += a0[u] * blo.y;
                    acc[0][2] += a0[u] * blo.z; acc[0][3] += a0[u] * blo.w;
                    acc[0][4] += a0[u] * bhi.x; acc[0][5] += a0[u] * bhi.y;
                    acc[0][6] += a0[u] * bhi.z; acc[0][7] += a0[u] * bhi.w;
                    acc[1][0] += a1[u] * blo.x; acc[1][1] += a1[u] * blo.y;
                    acc[1][2] += a1[u] * blo.z; acc[1][3] += a1[u] * blo.w;
                    acc[1][4] += a1[u] * bhi.x; acc[1][5] += a1[u] * bhi.y;
                    acc[1][6] += a1[u] * bhi.z; acc[1][7] += a1[u] * bhi.w;
                }
            }
            float4 bl = *reinterpret_cast<const float4*>(bias + 4 * tx8);
            float4 bh = *reinterpret_cast<const float4*>(bias + 4 * tx8 + 32);
            #pragma unroll
            for (int j = 0; j < 2; j++) {
                float* row = ks + (r0 + j) * KST;
                *reinterpret_cast<float4*>(row + 4 * tx8) =
                    make_float4(acc[j][0] + bl.x, acc[j][1] + bl.y,
                                acc[j][2] + bl.z, acc[j][3] + bl.w);
                *reinterpret_cast<float4*>(row + 4 * tx8 + 32) =
                    make_float4(acc[j][4] + bh.x, acc[j][5] + bh.y,
                                acc[j][6] + bh.z, acc[j][7] + bh.w);
            }
        }
        __syncthreads();

        // ---- row norms (4 threads per row)
        {
            int n = tid >> 2, q = tid & 3;
            const float* kr = ks + n * KST + q * 16;
            float s = 0.f;
            #pragma unroll
            for (int i = 0; i < 16; i++) { float v = kr[i]; s += v * v; }
            red[n * 4 + q] = s;
        }
        __syncthreads();
        if (tid < TILE) {
            float s = red[tid*4] + red[tid*4+1] + red[tid*4+2] + red[tid*4+3];
            inv[tid] = (tid < valid) ? rsqrtf(s) : 0.f;
        }
        __syncthreads();
        // normalize k tile (also zeroes invalid rows)
        for (int i = tid; i < TILE * DHEAD; i += 256) {
            int n = i >> 6, m = i & 63;
            ks[n * KST + m] *= inv[n];
        }
        __syncthreads();

        // ---- ks_sum column partials
        {
            int m = tid & 63, rg = tid >> 6;
            float s = 0.f;
            #pragma unroll
            for (int r = 0; r < 16; r++) s += ks[(rg * 16 + r) * KST + m];
            red[rg * 64 + m] = s;
        }
        // ---- colsum of x (head-0 blocks only)
        if (h == 0) {
            float s = 0.f;
            #pragma unroll 8
            for (int n = 0; n < TILE; n++) s += xs[n * XSS + tid];
            cs[tid] += s;
        }
        __syncthreads();
        if (tid < DHEAD)
            kss[tid] += red[tid] + red[64 + tid] + red[128 + tid] + red[192 + tid];

        // ---- kv rank-update: kv[m][c] += sum_n ks[n][m]*xs[n][c]
        // per thread: m rows {4tyk..+3}, c cols {cc*64 + 4txk..+3} for cc 0..3
        {
            float a2[4][4][4];
            #pragma unroll
            for (int cc = 0; cc < 4; cc++)
                #pragma unroll
                for (int j = 0; j < 4; j++)
                    #pragma unroll
                    for (int p = 0; p < 4; p++) a2[cc][j][p] = 0.f;

            #pragma unroll 2
            for (int n = 0; n < TILE; n++) {
                float4 sv = *reinterpret_cast<const float4*>(ks + n * KST + 4 * tyk);
                float s0 = sv.x, s1 = sv.y, s2 = sv.z, s3 = sv.w;
                const float* xrow = xs + n * XSS + 4 * txk;
                #pragma unroll
                for (int cc = 0; cc < 4; cc++) {
                    float4 b = *reinterpret_cast<const float4*>(xrow + cc * 64);
                    a2[cc][0][0] += s0 * b.x; a2[cc][0][1] += s0 * b.y;
                    a2[cc][0][2] += s0 * b.z; a2[cc][0][3] += s0 * b.w;
                    a2[cc][1][0] += s1 * b.x; a2[cc][1][1] += s1 * b.y;
                    a2[cc][1][2] += s1 * b.z; a2[cc][1][3] += s1 * b.w;
                    a2[cc][2][0] += s2 * b.x; a2[cc][2][1] += s2 * b.y;
                    a2[cc][2][2] += s2 * b.z; a2[cc][2][3] += s2 * b.w;
                    a2[cc][3][0] += s3 * b.x; a2[cc][3][1] += s3 * b.y;
                    a2[cc][3][2] += s3 * b.z; a2[cc][3][3] += s3 * b.w;
                }
            }
            #pragma unroll
            for (int cc = 0; cc < 4; cc++)
                #pragma unroll
                for (int j = 0; j < 4; j++) {
                    float* p = kv + (4 * tyk + j) * CIN + cc * 64 + 4 * txk;
                    float4 o = *reinterpret_cast<const float4*>(p);
                    o.x += a2[cc][j][0]; o.y += a2[cc][j][1];
                    o.z += a2[cc][j][2]; o.w += a2[cc][j][3];
                    *reinterpret_cast<float4*>(p) = o;
                }
        }
        __syncthreads();
    }

    // deterministic per-block partials
    for (int i = tid; i < DHEAD * CIN; i += 256)
        g_part_kvs[bx][h * DHEAD * CIN + i] = kv[i];
    if (tid < DHEAD) g_part_kss[bx][h * DHEAD + tid] = kss[tid];
    if (h == 0 && tid < CIN) g_part_cs[bx][tid] = cs[tid];
}

// =====================================================================
// Fixed-order reduction of per-block partials
// =====================================================================
__global__ void reduce_kernel()
{
    int i = blockIdx.x * 256 + threadIdx.x;
    if (i < NHEADS * DHEAD * CIN) {
        float s = 0.f;
        #pragma unroll 1
        for (int b = 0; b < BPH; b++) s += g_part_kvs[b][i];
        g_kvs[i] = s;
    }
    if (i < NHEADS * DHEAD) {
        float s = 0.f;
        for (int b = 0; b < BPH; b++) s += g_part_kss[b][i];
        g_kssum[i] = s;
    }
    if (i < CIN) {
        float s = 0.f;
        for (int b = 0; b < BPH; b++) s += g_part_cs[b][i];
        g_colsum[i] = s;
    }
}

// =====================================================================
// Phase B: q-projection + normalize + output
// =====================================================================
__global__ __launch_bounds__(256, 1)
void phaseB_kernel(const float* __restrict__ x,
                   const float* __restrict__ Wq,
                   const float* __restrict__ bq,
                   float* __restrict__ out)
{
    const int h   = blockIdx.y;
    const int tid = threadIdx.x;

    float* xs   = smf;                      // [TILE][XSS]
    float* wt   = xs   + TILE * XSS;        // [CIN][DHEAD]
    float* kvs  = wt   + CIN * DHEAD;       // [DHEAD][CIN]
    float* qs   = kvs  + DHEAD * CIN;       // [TILE][KST]
    float* bias = qs   + TILE * KST;        // [DHEAD]
    float* kss  = bias + DHEAD;             // [DHEAD]
    float* cs   = kss  + DHEAD;             // [CIN]
    float* red  = cs   + CIN;               // [256]
    float* red2 = red  + 256;               // [256]
    float* inv  = red2 + 256;               // [TILE]
    float* rno  = inv  + TILE;              // [TILE]

    for (int i = tid; i < DHEAD * CIN; i += 256) {
        int c = i & (CIN - 1);
        int m = i >> 8;
        wt[c * DHEAD + m] = Wq[(h * DHEAD + m) * CIN + c];
    }
    for (int i = tid; i < DHEAD * CIN; i += 256) kvs[i] = g_kvs[h * DHEAD * CIN + i];
    if (tid < DHEAD) { bias[tid] = bq[h * DHEAD + tid]; kss[tid] = g_kssum[h * DHEAD + tid]; }
    if (tid < CIN)   cs[tid] = g_colsum[tid];
    __syncthreads();

    const int tx8  = tid & 7;
    const int ty32 = tid >> 3;
    const int r0   = 2 * ty32;
    const int txo = tid & 15;
    const int tyo = tid >> 4;

    for (int tile = blockIdx.x; tile < NT; tile += BPH) {
        const int base  = tile * TILE;
        int valid = NNODES - base; if (valid > TILE) valid = TILE;

        for (int i = tid; i < TILE * 64; i += 256) {
            int n  = i >> 6;
            int c4 = (i & 63) << 2;
            float4 v = make_float4(0.f, 0.f, 0.f, 0.f);
            if (n < valid)
                v = *reinterpret_cast<const float4*>(x + (size_t)(base + n) * CIN + c4);
            *reinterpret_cast<float4*>(xs + n * XSS + c4) = v;
        }
        __syncthreads();

        // ---- q projection
        {
            float acc[2][8];
            #pragma unroll
            for (int j = 0; j < 2; j++)
                #pragma unroll
                for (int p = 0; p < 8; p++) acc[j][p] = 0.f;

            const float* xr0 = xs + r0 * XSS;
            const float* xr1 = xr0 + XSS;
            const float* wp0 = wt + 4 * tx8;
            #pragma unroll 2
            for (int c0 = 0; c0 < CIN; c0 += 4) {
                float4 av0 = *reinterpret_cast<const float4*>(xr0 + c0);
                float4 av1 = *reinterpret_cast<const float4*>(xr1 + c0);
                float a0[4] = {av0.x, av0.y, av0.z, av0.w};
                float a1[4] = {av1.x, av1.y, av1.z, av1.w};
                #pragma unroll
                for (int u = 0; u < 4; u++) {
                    const float* wc = wp0 + (c0 + u) * DHEAD;
                    float4 blo = *reinterpret_cast<const float4*>(wc);
                    float4 bhi = *reinterpret_cast<const float4*>(wc + 32);
                    acc[0][0] += a0[u] * blo.x; acc[0][1] += a0[u] * blo.y;
                    acc[0][2] += a0[u] * blo.z; acc[0][3] += a0[u] * blo.w;
                    acc[0][4] += a0[u] * bhi.x; acc[0][5] += a0[u] * bhi.y;
                    acc[0][6] += a0[u] * bhi.z; acc[0][7] += a0[u] * bhi.w;
                    acc[1][0] += a1[u] * blo.x; acc[1][1] += a1[u] * blo.y;
                    acc[1][2] += a1[u] * blo.z; acc[1][3] += a1[u] * blo.w;
                    acc[1][4] += a1[u] * bhi.x; acc[1][5] += a1[u] * bhi.y;
                    acc[1][6] += a1[u] * bhi.z; acc[1][7] += a1[u] * bhi.w;
                }
            }
            float4 bl = *reinterpret_cast<const float4*>(bias + 4 * tx8);
            float4 bh = *reinterpret_cast<const float4*>(bias + 4 * tx8 + 32);
            #pragma unroll
            for (int j = 0; j < 2; j++) {
                float* row = qs + (r0 + j) * KST;
                *reinterpret_cast<float4*>(row + 4 * tx8) =
                    make_float4(acc[j][0] + bl.x, acc[j][1] + bl.y,
                                acc[j][2] + bl.z, acc[j][3] + bl.w);
                *reinterpret_cast<float4*>(row + 4 * tx8 + 32) =
                    make_float4(acc[j][4] + bh.x, acc[j][5] + bh.y,
                                acc[j][6] + bh.z, acc[j][7] + bh.w);
            }
        }
        __syncthreads();

        // ---- row norms + dot(P, ks_sum)
        {
            int n = tid >> 2, q = tid & 3;
            const float* qr = qs + n * KST + q * 16;
            const float* kr = kss + q * 16;
            float s = 0.f, d = 0.f;
            #pragma unroll
            for (int i = 0; i < 16; i++) { float v = qr[i]; s += v * v; d += v * kr[i]; }
            red [n * 4 + q] = s;
            red2[n * 4 + q] = d;
        }
        __syncthreads();
        if (tid < TILE) {
            float s = red [tid*4] + red [tid*4+1] + red [tid*4+2] + red [tid*4+3];
            float d = red2[tid*4] + red2[tid*4+1] + red2[tid*4+2] + red2[tid*4+3];
            float iv = (tid < valid) ? rsqrtf(s) : 0.f;
            inv[tid] = iv;
            rno[tid] = 1.0f / (iv * d + (float)NNODES);
        }
        __syncthreads();
        for (int i = tid; i < TILE * DHEAD; i += 256) {
            int n = i >> 6, m = i & 63;
            qs[n * KST + m] *= inv[n];
        }
        __syncthreads();

        // ---- out[n][c] = (sum_m qs[n][m]*kvs[m][c] + colsum[c]) * rno[n]
        {
            float a2[4][4][4];
            #pragma unroll
            for (int cc = 0; cc < 4; cc++)
                #pragma unroll
                for (int j = 0; j < 4; j++)
                    #pragma unroll
                    for (int p = 0; p < 4; p++) a2[cc][j][p] = 0.f;

            const float* q0p = qs + (4 * tyo + 0) * KST;
            const float* q1p = qs + (4 * tyo + 1) * KST;
            const float* q2p = qs + (4 * tyo + 2) * KST;
            const float* q3p = qs + (4 * tyo + 3) * KST;

            for (int m0 = 0; m0 < DHEAD; m0 += 4) {
                float4 qv0 = *reinterpret_cast<const float4*>(q0p + m0);
                float4 qv1 = *reinterpret_cast<const float4*>(q1p + m0);
                float4 qv2 = *reinterpret_cast<const float4*>(q2p + m0);
                float4 qv3 = *reinterpret_cast<const float4*>(q3p + m0);
                float a0[4] = {qv0.x, qv0.y, qv0.z, qv0.w};
                float a1[4] = {qv1.x, qv1.y, qv1.z, qv1.w};
                float a2v[4] = {qv2.x, qv2.y, qv2.z, qv2.w};
                float a3[4] = {qv3.x, qv3.y, qv3.z, qv3.w};
                #pragma unroll
                for (int u = 0; u < 4; u++) {
                    const float* krow = kvs + (m0 + u) * CIN + 4 * txo;
                    #pragma unroll
                    for (int cc = 0; cc < 4; cc++) {
                        float4 b = *reinterpret_cast<const float4*>(krow + cc * 64);
                        a2[cc][0][0] += a0[u] * b.x; a2[cc][0][1] += a0[u] * b.y;
                        a2[cc][0][2] += a0[u] * b.z; a2[cc][0][3] += a0[u] * b.w;
                        a2[cc][1][0] += a1[u] * b.x; a2[cc][1][1] += a1[u] * b.y;
                        a2[cc][1][2] += a1[u] * b.z; a2[cc][1][3] += a1[u] * b.w;
                        a2[cc][2][0] += a2v[u] * b.x; a2[cc][2][1] += a2v[u] * b.y;
                        a2[cc][2][2] += a2v[u] * b.z; a2[cc][2][3] += a2v[u] * b.w;
                        a2[cc][3][0] += a3[u] * b.x; a2[cc][3][1] += a3[u] * b.y;
                        a2[cc][3][2] += a3[u] * b.z; a2[cc][3][3] += a3[u] * b.w;
                    }
                }
            }

            #pragma unroll
            for (int cc = 0; cc < 4; cc++) {
                float4 cv = *reinterpret_cast<const float4*>(cs + cc * 64 + 4 * txo);
                #pragma unroll
                for (int j = 0; j < 4; j++) {
                    int n = 4 * tyo + j;
                    if (n < valid) {
                        float r = rno[n];
                        float4 o;
                        o.x = (a2[cc][j][0] + cv.x) * r;
                        o.y = (a2[cc][j][1] + cv.y) * r;
                        o.z = (a2[cc][j][2] + cv.z) * r;
                        o.w = (a2[cc][j][3] + cv.w) * r;
                        *reinterpret_cast<float4*>(
                            out + (size_t)(base + n) * (NHEADS * CIN) + h * CIN + cc * 64 + 4 * txo) = o;
                    }
                }
            }
        }
        __syncthreads();
    }
}

// =====================================================================
extern "C" void kernel_launch(void* const* d_in, const int* in_sizes, int n_in,
                              void* d_out, int out_size)
{
    const float* x    = (const float*)d_in[0];
    const float* Wq_w = (const float*)d_in[1];
    const float* Wq_b = (const float*)d_in[2];
    const float* Wk_w = (const float*)d_in[3];
    const float* Wk_b = (const float*)d_in[4];
    float* out = (float*)d_out;

    const int smemA = (TILE*XSS + CIN*DHEAD + DHEAD*CIN + TILE*KST
                       + DHEAD + DHEAD + CIN + 256 + TILE) * (int)sizeof(float);
    const int smemB = (TILE*XSS + CIN*DHEAD + DHEAD*CIN + TILE*KST
                       + DHEAD + DHEAD + CIN + 256 + 256 + TILE + TILE) * (int)sizeof(float);

    cudaFuncSetAttribute(phaseA_kernel, cudaFuncAttributeMaxDynamicSharedMemorySize, smemA);
    cudaFuncSetAttribute(phaseB_kernel, cudaFuncAttributeMaxDynamicSharedMemorySize, smemB);

    phaseA_kernel<<<dim3(BPH, NHEADS), 256, smemA>>>(x, Wk_w, Wk_b);
    reduce_kernel<<<256, 256>>>();
    phaseB_kernel<<<dim3(BPH, NHEADS), 256, smemB>>>(x, Wq_w, Wq_b, out);
}

// round 5
// speedup vs baseline: 1.6707x; 1.6707x over previous
#include <cuda_runtime.h>
#include <math.h>
#include <stdint.h>

#define NNODES 100000
#define CIN    256
#define NHEADS 4
#define DHEAD  64
#define BPH    37
#define TA     64
#define NTA    ((NNODES + TA - 1) / TA)   // 1563
#define TB     32
#define NTB    (NNODES / TB)              // 3125 exactly
#define KST    68

// ---------------- helpers ----------------
__device__ __forceinline__ float rna(float f) {
    unsigned int u;
    asm("cvt.rna.tf32.f32 %0, %1;" : "=r"(u) : "f"(f));
    return __uint_as_float(u);
}
__device__ __forceinline__ void mma8(float c[4], uint4 a, uint2 b) {
    asm volatile("mma.sync.aligned.m16n8k8.row.col.f32.tf32.tf32.f32 "
        "{%0,%1,%2,%3}, {%4,%5,%6,%7}, {%8,%9}, {%0,%1,%2,%3};"
        : "+f"(c[0]), "+f"(c[1]), "+f"(c[2]), "+f"(c[3])
        : "r"(a.x), "r"(a.y), "r"(a.z), "r"(a.w), "r"(b.x), "r"(b.y));
}

// ---------------- device scratch (no allocations) ----------------
__device__ float g_WB[2][NHEADS][16384];      // B-perm tf32 weights: [0]=Wq [1]=Wk
__device__ float g_kvsB[NHEADS][16384];       // B-perm tf32 kvs for phase B
__device__ float g_part_kvs[BPH][NHEADS * DHEAD * CIN];
__device__ float g_part_kss[BPH][NHEADS * DHEAD];
__device__ float g_part_cs [BPH][CIN];
__device__ float g_kvs   [NHEADS * DHEAD * CIN];
__device__ float g_kssum [NHEADS * DHEAD];
__device__ float g_colsum[CIN];

extern __shared__ float smf[];

// =====================================================================
// Prep: W -> B-fragment-permuted tf32 layout
// j = ((nt*32+kb)*32+lane)*2+e ; value = Wt[c][m], m=nt*8+lane/4,
// c = kb*8 + e*4 + lane%4 ; Wt[c][m] = W[(h*64+m)*256+c]
// =====================================================================
__global__ void prep_kernel(const float* __restrict__ Wq,
                            const float* __restrict__ Wk)
{
    int i = blockIdx.x * 256 + threadIdx.x;
    if (i >= 2 * NHEADS * 16384) return;
    int which = i >> 16;            // 0=q, 1=k
    int rem   = i & 65535;
    int hh    = rem >> 14;
    int j     = rem & 16383;
    int e    = j & 1;
    int lane = (j >> 1) & 31;
    int kb   = (j >> 6) & 31;
    int nt   = j >> 11;
    int m = nt * 8 + (lane >> 2);
    int c = kb * 8 + e * 4 + (lane & 3);
    const float* W = which ? Wk : Wq;
    g_WB[which][hh][j] = rna(W[(hh * 64 + m) * 256 + c]);
}

// =====================================================================
// Phase A: k-projection (mma) + normalize + kv (mma, reg-resident C)
// smem: xsA 16384 | wsB 16384 | ksb 4352 | kstA 4096 | bias 64 | kss 64
//       red 256 | inv 64 | csred 1024   => 42688 floats = 170752 B
// =====================================================================
__global__ __launch_bounds__(256, 1)
void phaseA_kernel(const float* __restrict__ x, const float* __restrict__ bk)
{
    const int h = blockIdx.y, bx = blockIdx.x, tid = threadIdx.x;
    const int lane = tid & 31, w = tid >> 5;
    const int gq = lane >> 2, ct = lane & 3;

    float* xsA  = smf;             // (4 s)(32 kb)(32 lane)(4 e)
    float* wsB  = xsA + 16384;     // (8 nt)(32 kb)(32 lane)(2 e)
    float* ksb  = wsB + 16384;     // [64][KST]
    float* kstA = ksb + 4352;      // (4 sm)(8 kbn)(32)(4)
    float* bias = kstA + 4096;
    float* kss  = bias + 64;
    float* red  = kss + 64;
    float* inv  = red + 256;
    float* csred= inv + 64;        // [256 c][4 grp]

    for (int i = tid; i < 16384; i += 256) wsB[i] = g_WB[1][h][i];
    if (tid < 64) { bias[tid] = bk[h * 64 + tid]; kss[tid] = 0.f; }
    __syncthreads();

    float4 csacc = make_float4(0.f, 0.f, 0.f, 0.f);
    float kvC[16][4];
    #pragma unroll
    for (int t = 0; t < 16; t++) { kvC[t][0]=0.f; kvC[t][1]=0.f; kvC[t][2]=0.f; kvC[t][3]=0.f; }

    const int ps = w >> 1, pnh = w & 1;   // proj: m-slab(4) x n-half(2)
    const int km = w >> 1, kch = w & 1;   // kv:   m-slab(4) x c-half(2)

    for (int tile = bx; tile < NTA; tile += BPH) {
        const int base = tile * TA;
        const int valid = (NNODES - base < TA) ? (NNODES - base) : TA;

        // ---- load x tile -> A-perm tf32 smem (+ exact colsum partials)
        for (int i = tid; i < TA * 64; i += 256) {
            int n = i >> 6, c4 = (i & 63) << 2;
            float4 v = make_float4(0.f, 0.f, 0.f, 0.f);
            if (n < valid) v = *(const float4*)(x + (size_t)(base + n) * CIN + c4);
            csacc.x += v.x; csacc.y += v.y; csacc.z += v.z; csacc.w += v.w;
            int s = n >> 4, h8 = (n >> 3) & 1, g = n & 7;
            int kb = c4 >> 3, h4 = (c4 >> 2) & 1;
            float* p = xsA + ((s * 32 + kb) * 32 + g * 4) * 4 + (h8 + 2 * h4);
            p[0] = rna(v.x); p[4] = rna(v.y); p[8] = rna(v.z); p[12] = rna(v.w);
        }
        __syncthreads();

        // ---- k projection: P[64][64] = X @ WkT   (per warp: 16 rows x 32 cols)
        {
            float pc[4][4];
            #pragma unroll
            for (int t = 0; t < 4; t++) { pc[t][0]=0.f; pc[t][1]=0.f; pc[t][2]=0.f; pc[t][3]=0.f; }
            #pragma unroll 4
            for (int kb = 0; kb < 32; kb++) {
                uint4 a = *(const uint4*)(xsA + ((ps * 32 + kb) * 32 + lane) * 4);
                #pragma unroll
                for (int t = 0; t < 4; t++) {
                    int nt = pnh * 4 + t;
                    uint2 b = *(const uint2*)(wsB + ((nt * 32 + kb) * 32 + lane) * 2);
                    mma8(pc[t], a, b);
                }
            }
            int r0 = ps * 16 + gq, r1 = r0 + 8;
            #pragma unroll
            for (int t = 0; t < 4; t++) {
                int cb = (pnh * 4 + t) * 8 + 2 * ct;
                float b0 = bias[cb], b1 = bias[cb + 1];
                *(float2*)(ksb + r0 * KST + cb) = make_float2(pc[t][0] + b0, pc[t][1] + b1);
                *(float2*)(ksb + r1 * KST + cb) = make_float2(pc[t][2] + b0, pc[t][3] + b1);
            }
        }
        __syncthreads();

        // ---- row norms
        {
            int n = tid >> 2, q = tid & 3;
            const float* kr = ksb + n * KST + q * 16;
            float s = 0.f;
            #pragma unroll
            for (int i2 = 0; i2 < 16; i2++) { float v = kr[i2]; s += v * v; }
            red[n * 4 + q] = s;
        }
        __syncthreads();
        if (tid < TA) {
            float s = red[tid*4] + red[tid*4+1] + red[tid*4+2] + red[tid*4+3];
            inv[tid] = (tid < valid) ? rsqrtf(s) : 0.f;
        }
        __syncthreads();
        for (int i = tid; i < TA * 64; i += 256) {
            int n = i >> 6, m = i & 63;
            ksb[n * KST + m] *= inv[n];
        }
        __syncthreads();

        // ---- ks_sum partials
        {
            int m = tid & 63, rg = tid >> 6;
            float s = 0.f;
            #pragma unroll
            for (int r = 0; r < 16; r++) s += ksb[(rg * 16 + r) * KST + m];
            red[rg * 64 + m] = s;
        }
        __syncthreads();
        if (tid < 64) kss[tid] += red[tid] + red[64+tid] + red[128+tid] + red[192+tid];

        // ---- repack normalized ks -> kstA (A-perm tf32; A[m][n] = ks[n][m])
        for (int i = tid; i < 4096; i += 256) {
            int e = i & 3, l2 = (i >> 2) & 31, kbn = (i >> 7) & 7, sm = i >> 10;
            int m = sm * 16 + (e & 1) * 8 + (l2 >> 2);
            int n = kbn * 8 + (e >> 1) * 4 + (l2 & 3);
            kstA[i] = rna(ksb[n * KST + m]);
        }
        __syncthreads();

        // ---- kv += ks^T @ x  (M=64 m, N=256 c, K=64 n); C in registers
        {
            #pragma unroll
            for (int kb = 0; kb < 8; kb++) {
                uint4 a = *(const uint4*)(kstA + ((km * 8 + kb) * 32 + lane) * 4);
                int off0 = (ct * 4 + (gq & 3)) * 4 + (kb & 1) + 2 * (gq >> 2);
                const float* pb = xsA + (kb >> 1) * 4096 + kch * 2048 + off0;
                #pragma unroll
                for (int t = 0; t < 16; t++) {
                    uint2 b;
                    b.x = __float_as_uint(pb[t * 128]);
                    b.y = __float_as_uint(pb[t * 128 + 64]);
                    mma8(kvC[t], a, b);
                }
            }
        }
        __syncthreads();
    }

    // ---- deterministic per-block partials
    {
        float* dst = g_part_kvs[bx] + h * (DHEAD * CIN);
        #pragma unroll
        for (int t = 0; t < 16; t++) {
            int c0 = (kch * 16 + t) * 8 + 2 * ct;
            int m0 = km * 16 + gq;
            dst[m0 * 256 + c0]           = kvC[t][0];
            dst[m0 * 256 + c0 + 1]       = kvC[t][1];
            dst[(m0 + 8) * 256 + c0]     = kvC[t][2];
            dst[(m0 + 8) * 256 + c0 + 1] = kvC[t][3];
        }
    }
    if (tid < 64) g_part_kss[bx][h * 64 + tid] = kss[tid];
    {
        int c4 = (tid & 63) * 4, grp = tid >> 6;
        csred[(c4+0)*4+grp] = csacc.x; csred[(c4+1)*4+grp] = csacc.y;
        csred[(c4+2)*4+grp] = csacc.z; csred[(c4+3)*4+grp] = csacc.w;
    }
    __syncthreads();
    if (h == 0 && tid < CIN)
        g_part_cs[bx][tid] = csred[tid*4] + csred[tid*4+1] + csred[tid*4+2] + csred[tid*4+3];
}

// =====================================================================
// Reduce: fixed-order partial sums; also emit B-perm tf32 kvs
// =====================================================================
__global__ void reduce_kernel()
{
    int i = blockIdx.x * 256 + threadIdx.x;
    if (i < NHEADS * DHEAD * CIN) {
        float s = 0.f;
        #pragma unroll 1
        for (int b = 0; b < BPH; b++) s += g_part_kvs[b][i];
        g_kvs[i] = s;
        int hh = i >> 14, rem = i & 16383, m = rem >> 8, c = rem & 255;
        int ctile = c >> 3, lane = (c & 7) * 4 + (m & 3);
        int kbm = m >> 3, e = (m >> 2) & 1;
        g_kvsB[hh][((ctile * 8 + kbm) * 32 + lane) * 2 + e] = rna(s);
    }
    if (i < NHEADS * DHEAD) {
        float s = 0.f;
        for (int b = 0; b < BPH; b++) s += g_part_kss[b][i];
        g_kssum[i] = s;
    }
    if (i < CIN) {
        float s = 0.f;
        for (int b = 0; b < BPH; b++) s += g_part_cs[b][i];
        g_colsum[i] = s;
    }
}

// =====================================================================
// Phase B: q-projection (mma) + normalize + out GEMM (mma)
// smem: xsA 8192 | wsB 16384 | kvsB 16384 | qsb 2176 | qstA 2048 |
//       bias 64 | kss 64 | cs 256 | red 256 | red2 256 | inv 32 | rno 32
//       => 46144 floats = 184576 B
// =====================================================================
__global__ __launch_bounds__(256, 1)
void phaseB_kernel(const float* __restrict__ x, const float* __restrict__ bq,
                   float* __restrict__ out)
{
    const int h = blockIdx.y, tid = threadIdx.x;
    const int lane = tid & 31, w = tid >> 5;
    const int gq = lane >> 2, ct = lane & 3;

    float* xsA  = smf;              // (2 s)(32 kb)(32)(4)
    float* wsB  = xsA + 8192;       // (8 nt)(32 kb)(32)(2)
    float* kvsB = wsB + 16384;      // (32 ctile)(8 kb)(32)(2)
    float* qsb  = kvsB + 16384;     // [32][KST]
    float* qstA = qsb + 2176;       // (2 sn)(8 kbm)(32)(4)
    float* bias = qstA + 2048;
    float* kss  = bias + 64;
    float* cs   = kss + 64;
    float* red  = cs + 256;
    float* red2 = red + 256;
    float* inv  = red2 + 256;
    float* rno  = inv + 32;

    for (int i = tid; i < 16384; i += 256) wsB[i]  = g_WB[0][h][i];
    for (int i = tid; i < 16384; i += 256) kvsB[i] = g_kvsB[h][i];
    if (tid < 64) { bias[tid] = bq[h * 64 + tid]; kss[tid] = g_kssum[h * 64 + tid]; }
    if (tid < CIN) cs[tid] = g_colsum[tid];
    __syncthreads();

    const int ps = w >> 2, pq = w & 3;   // proj: slab(2) x quarter(4)
    const int sn = w >> 2, ch = w & 3;   // out:  slab(2) x c-quarter(4)

    for (int tile = blockIdx.x; tile < NTB; tile += BPH) {
        const int base = tile * TB;

        for (int i = tid; i < TB * 64; i += 256) {
            int n = i >> 6, c4 = (i & 63) << 2;
            float4 v = *(const float4*)(x + (size_t)(base + n) * CIN + c4);
            int s = n >> 4, h8 = (n >> 3) & 1, g = n & 7;
            int kb = c4 >> 3, h4 = (c4 >> 2) & 1;
            float* p = xsA + ((s * 32 + kb) * 32 + g * 4) * 4 + (h8 + 2 * h4);
            p[0] = rna(v.x); p[4] = rna(v.y); p[8] = rna(v.z); p[12] = rna(v.w);
        }
        __syncthreads();

        // ---- q projection: P[32][64]
        {
            float pc[2][4];
            pc[0][0]=0.f; pc[0][1]=0.f; pc[0][2]=0.f; pc[0][3]=0.f;
            pc[1][0]=0.f; pc[1][1]=0.f; pc[1][2]=0.f; pc[1][3]=0.f;
            #pragma unroll 4
            for (int kb = 0; kb < 32; kb++) {
                uint4 a = *(const uint4*)(xsA + ((ps * 32 + kb) * 32 + lane) * 4);
                #pragma unroll
                for (int t = 0; t < 2; t++) {
                    int nt = pq * 2 + t;
                    uint2 b = *(const uint2*)(wsB + ((nt * 32 + kb) * 32 + lane) * 2);
                    mma8(pc[t], a, b);
                }
            }
            int r0 = ps * 16 + gq, r1 = r0 + 8;
            #pragma unroll
            for (int t = 0; t < 2; t++) {
                int cb = (pq * 2 + t) * 8 + 2 * ct;
                float b0 = bias[cb], b1 = bias[cb + 1];
                *(float2*)(qsb + r0 * KST + cb) = make_float2(pc[t][0] + b0, pc[t][1] + b1);
                *(float2*)(qsb + r1 * KST + cb) = make_float2(pc[t][2] + b0, pc[t][3] + b1);
            }
        }
        __syncthreads();

        // ---- norms + dot(P, ks_sum)
        {
            int n = tid >> 3, q8 = tid & 7;
            const float* qr = qsb + n * KST + q8 * 8;
            const float* kr = kss + q8 * 8;
            float s = 0.f, d = 0.f;
            #pragma unroll
            for (int i2 = 0; i2 < 8; i2++) { float v = qr[i2]; s += v * v; d += v * kr[i2]; }
            red[n * 8 + q8] = s; red2[n * 8 + q8] = d;
        }
        __syncthreads();
        if (tid < TB) {
            float s = 0.f, d = 0.f;
            #pragma unroll
            for (int j = 0; j < 8; j++) { s += red[tid*8+j]; d += red2[tid*8+j]; }
            float iv = rsqrtf(s);
            inv[tid] = iv;
            rno[tid] = 1.0f / (iv * d + (float)NNODES);
        }
        __syncthreads();

        // ---- repack qs*inv -> qstA (A-perm tf32)
        for (int i = tid; i < 2048; i += 256) {
            int e = i & 3, l2 = (i >> 2) & 31, kbm = (i >> 7) & 7, s2 = i >> 10;
            int m = kbm * 8 + (e >> 1) * 4 + (l2 & 3);
            int n = s2 * 16 + (e & 1) * 8 + (l2 >> 2);
            qstA[i] = rna(qsb[n * KST + m] * inv[n]);
        }
        __syncthreads();

        // ---- out[n][c] = (qs @ kvs + colsum) * rno
        {
            float oc[8][4];
            #pragma unroll
            for (int t = 0; t < 8; t++) { oc[t][0]=0.f; oc[t][1]=0.f; oc[t][2]=0.f; oc[t][3]=0.f; }
            #pragma unroll
            for (int kb = 0; kb < 8; kb++) {
                uint4 a = *(const uint4*)(qstA + ((sn * 8 + kb) * 32 + lane) * 4);
                #pragma unroll
                for (int t = 0; t < 8; t++) {
                    int ctile = ch * 8 + t;
                    uint2 b = *(const uint2*)(kvsB + ((ctile * 8 + kb) * 32 + lane) * 2);
                    mma8(oc[t], a, b);
                }
            }
            int n0 = sn * 16 + gq;
            float r0v = rno[n0], r1v = rno[n0 + 8];
            #pragma unroll
            for (int t = 0; t < 8; t++) {
                int c0 = (ch * 8 + t) * 8 + 2 * ct;
                float cv0 = cs[c0], cv1 = cs[c0 + 1];
                float* o0 = out + (size_t)(base + n0) * (NHEADS * CIN) + h * CIN + c0;
                float* o1 = out + (size_t)(base + n0 + 8) * (NHEADS * CIN) + h * CIN + c0;
                *(float2*)o0 = make_float2((oc[t][0] + cv0) * r0v, (oc[t][1] + cv1) * r0v);
                *(float2*)o1 = make_float2((oc[t][2] + cv0) * r1v, (oc[t][3] + cv1) * r1v);
            }
        }
        __syncthreads();
    }
}

// =====================================================================
extern "C" void kernel_launch(void* const* d_in, const int* in_sizes, int n_in,
                              void* d_out, int out_size)
{
    const float* x    = (const float*)d_in[0];
    const float* Wq_w = (const float*)d_in[1];
    const float* Wq_b = (const float*)d_in[2];
    const float* Wk_w = (const float*)d_in[3];
    const float* Wk_b = (const float*)d_in[4];
    float* out = (float*)d_out;

    const int smemA = 42688 * (int)sizeof(float);   // 170752 B
    const int smemB = 46144 * (int)sizeof(float);   // 184576 B

    cudaFuncSetAttribute(phaseA_kernel, cudaFuncAttributeMaxDynamicSharedMemorySize, smemA);
    cudaFuncSetAttribute(phaseB_kernel, cudaFuncAttributeMaxDynamicSharedMemorySize, smemB);

    prep_kernel<<<(2 * NHEADS * 16384 + 255) / 256, 256>>>(Wq_w, Wk_w);
    phaseA_kernel<<<dim3(BPH, NHEADS), 256, smemA>>>(x, Wk_b);
    reduce_kernel<<<256, 256>>>();
    phaseB_kernel<<<dim3(BPH, NHEADS), 256, smemB>>>(x, Wq_b, out);
}

// round 6
// speedup vs baseline: 2.3830x; 1.4263x over previous
#include <cuda_runtime.h>
#include <math.h>
#include <stdint.h>

#define NNODES 100000
#define CIN    256
#define NHEADS 4
#define DHEAD  64
#define BPH    37
#define TILE   64
#define NT     ((NNODES + TILE - 1) / TILE)   // 1563
#define XS     260                            // xsA stride (== 4 mod 32: A-frag clean)
#define KS     72                             // ks stride  (== 8 mod 32: transposed-A clean)
#define QS     68                             // qs stride  (== 4 mod 32: A-frag clean)

// ---------------- helpers ----------------
__device__ __forceinline__ float rna(float f) {
    unsigned int u;
    asm("cvt.rna.tf32.f32 %0, %1;" : "=r"(u) : "f"(f));
    return __uint_as_float(u);
}
__device__ __forceinline__ unsigned int fu(float f) { return __float_as_uint(f); }
__device__ __forceinline__ void mma8(float c[4], uint4 a, uint2 b) {
    asm volatile("mma.sync.aligned.m16n8k8.row.col.f32.tf32.tf32.f32 "
        "{%0,%1,%2,%3}, {%4,%5,%6,%7}, {%8,%9}, {%0,%1,%2,%3};"
        : "+f"(c[0]), "+f"(c[1]), "+f"(c[2]), "+f"(c[3])
        : "r"(a.x), "r"(a.y), "r"(a.z), "r"(a.w), "r"(b.x), "r"(b.y));
}

// ---------------- device scratch ----------------
__device__ float g_part_kvs[BPH][NHEADS * DHEAD * CIN];
__device__ float g_part_kss[BPH][NHEADS * DHEAD];
__device__ float g_part_cs [BPH][CIN];
__device__ float g_kvs   [NHEADS * DHEAD * CIN];
__device__ float g_kssum [NHEADS * DHEAD];
__device__ float g_colsum[CIN];

extern __shared__ float smf[];

// =====================================================================
// Phase A: k-projection (mma) + normalize + kv (mma, reg-resident C)
// smem floats: xsA 16640 | xsB 16384 | wt 16384 | ks 4608 | bias 64 |
//              kss 64 | red 256 | inv 64 | csred 1024  = 55488 (221952 B)
// =====================================================================
__global__ __launch_bounds__(256, 1)
void phaseA_kernel(const float* __restrict__ x,
                   const float* __restrict__ Wk,
                   const float* __restrict__ bk)
{
    const int h = blockIdx.y, bx = blockIdx.x, tid = threadIdx.x;
    const int lane = tid & 31, w = tid >> 5;
    const int gq = lane >> 2, ct = lane & 3;

    float* xsA  = smf;             // [64][260]
    float* xsB  = xsA + 16640;     // [64][256] swizzled: phys_c = c ^ (8*(n&3))
    float* wt   = xsB + 16384;     // [256][64] swizzled: phys_m = m ^ (8*(c&3))
    float* ks   = wt  + 16384;     // [64][KS]
    float* bias = ks  + 4608;
    float* kss  = bias + 64;
    float* red  = kss + 64;
    float* inv  = red + 256;
    float* csred= inv + 64;        // [256][4]

    // stage Wk^T tf32 swizzled: wt[c][m]
    for (int i = tid; i < 16384; i += 256) {
        int c = i >> 6, m = i & 63;
        wt[c * 64 + (m ^ (8 * (c & 3)))] = rna(Wk[(h * 64 + m) * 256 + c]);
    }
    if (tid < 64) { bias[tid] = bk[h * 64 + tid]; kss[tid] = 0.f; }
    __syncthreads();

    const int ps = w >> 1, nh = w & 1;   // proj: 4 row-slabs x 2 n-halves
    const int km = w >> 1, ch = w & 1;   // kv:   4 m-slabs  x 2 c-halves

    float kvC[16][4];
    #pragma unroll
    for (int t = 0; t < 16; t++) { kvC[t][0]=0.f; kvC[t][1]=0.f; kvC[t][2]=0.f; kvC[t][3]=0.f; }
    float4 csacc = make_float4(0.f, 0.f, 0.f, 0.f);

    for (int tile = bx; tile < NT; tile += BPH) {
        const int base = tile * TILE;
        const int valid = (NNODES - base < TILE) ? (NNODES - base) : TILE;

        // ---- load x tile (two smem copies), exact colsum partials
        for (int i = tid; i < TILE * 64; i += 256) {
            int n = i >> 6, c4 = (i & 63) << 2;
            float4 v = make_float4(0.f, 0.f, 0.f, 0.f);
            if (n < valid) v = *(const float4*)(x + (size_t)(base + n) * CIN + c4);
            csacc.x += v.x; csacc.y += v.y; csacc.z += v.z; csacc.w += v.w;
            float4 r = make_float4(rna(v.x), rna(v.y), rna(v.z), rna(v.w));
            *(float4*)(xsA + n * XS + c4) = r;
            *(float4*)(xsB + n * 256 + (c4 ^ (8 * (n & 3)))) = r;
        }
        __syncthreads();

        // ---- k projection: P[64][64] = X @ WkT
        {
            float pc[4][4];
            #pragma unroll
            for (int t = 0; t < 4; t++) { pc[t][0]=0.f; pc[t][1]=0.f; pc[t][2]=0.f; pc[t][3]=0.f; }
            #pragma unroll 4
            for (int kb = 0; kb < 32; kb++) {
                const float* xr = xsA + (ps * 16 + gq) * XS + kb * 8 + ct;
                uint4 a;
                a.x = fu(xr[0]); a.y = fu(xr[8 * XS]);
                a.z = fu(xr[4]); a.w = fu(xr[8 * XS + 4]);
                #pragma unroll
                for (int t = 0; t < 4; t++) {
                    int nt = nh * 4 + t;
                    const float* wp = wt + (kb * 8 + ct) * 64 + ((nt * 8 + gq) ^ (8 * ct));
                    uint2 b; b.x = fu(wp[0]); b.y = fu(wp[4 * 64]);
                    mma8(pc[t], a, b);
                }
            }
            int r0 = ps * 16 + gq;
            #pragma unroll
            for (int t = 0; t < 4; t++) {
                int cb = (nh * 4 + t) * 8 + 2 * ct;
                float b0 = bias[cb], b1 = bias[cb + 1];
                *(float2*)(ks + r0 * KS + cb)       = make_float2(pc[t][0] + b0, pc[t][1] + b1);
                *(float2*)(ks + (r0 + 8) * KS + cb) = make_float2(pc[t][2] + b0, pc[t][3] + b1);
            }
        }
        __syncthreads();

        // ---- row norms
        {
            int n = tid >> 2, q = tid & 3;
            const float* kr = ks + n * KS + q * 16;
            float s = 0.f;
            #pragma unroll
            for (int i2 = 0; i2 < 16; i2++) { float v = kr[i2]; s += v * v; }
            red[n * 4 + q] = s;
        }
        __syncthreads();
        if (tid < 64) {
            float s = red[tid*4] + red[tid*4+1] + red[tid*4+2] + red[tid*4+3];
            inv[tid] = (tid < valid) ? rsqrtf(s) : 0.f;
        }
        __syncthreads();
        // ---- normalize + tf32-round in place
        for (int i = tid; i < TILE * 64; i += 256) {
            int n = i >> 6, m = i & 63;
            ks[n * KS + m] = rna(ks[n * KS + m] * inv[n]);
        }
        __syncthreads();
        // ---- ks_sum partials
        {
            int m = tid & 63, rg = tid >> 6;
            float s = 0.f;
            #pragma unroll
            for (int r = 0; r < 16; r++) s += ks[(rg * 16 + r) * KS + m];
            red[rg * 64 + m] = s;
        }
        __syncthreads();
        if (tid < 64) kss[tid] += red[tid] + red[64+tid] + red[128+tid] + red[192+tid];

        // ---- kv += ks^T @ x  (A from ks transposed-clean, B from xsB swizzle-clean)
        {
            #pragma unroll
            for (int kb = 0; kb < 8; kb++) {
                const float* kp = ks + (kb * 8 + ct) * KS + km * 16 + gq;
                uint4 a;
                a.x = fu(kp[0]); a.y = fu(kp[8]);
                a.z = fu(kp[4 * KS]); a.w = fu(kp[4 * KS + 8]);
                const float* xb0 = xsB + (kb * 8 + ct) * 256;
                const float* xb1 = xsB + (kb * 8 + ct + 4) * 256;
                const int sw = 8 * ct;
                #pragma unroll
                for (int t = 0; t < 16; t++) {
                    int c = ch * 128 + t * 8 + gq;
                    uint2 b; b.x = fu(xb0[c ^ sw]); b.y = fu(xb1[c ^ sw]);
                    mma8(kvC[t], a, b);
                }
            }
        }
        __syncthreads();
    }

    // ---- deterministic per-block partials
    {
        float* dst = g_part_kvs[bx] + h * (DHEAD * CIN);
        #pragma unroll
        for (int t = 0; t < 16; t++) {
            int c0 = ch * 128 + t * 8 + 2 * ct;
            int m0 = km * 16 + gq;
            dst[m0 * 256 + c0]           = kvC[t][0];
            dst[m0 * 256 + c0 + 1]       = kvC[t][1];
            dst[(m0 + 8) * 256 + c0]     = kvC[t][2];
            dst[(m0 + 8) * 256 + c0 + 1] = kvC[t][3];
        }
    }
    if (tid < 64) g_part_kss[bx][h * 64 + tid] = kss[tid];
    {
        int c4 = (tid & 63) * 4, grp = tid >> 6;
        csred[(c4+0)*4+grp] = csacc.x; csred[(c4+1)*4+grp] = csacc.y;
        csred[(c4+2)*4+grp] = csacc.z; csred[(c4+3)*4+grp] = csacc.w;
    }
    __syncthreads();
    if (h == 0 && tid < CIN)
        g_part_cs[bx][tid] = csred[tid*4] + csred[tid*4+1] + csred[tid*4+2] + csred[tid*4+3];
}

// =====================================================================
// Reduce: fixed-order partial sums
// =====================================================================
__global__ void reduce_kernel()
{
    int i = blockIdx.x * 256 + threadIdx.x;
    if (i < NHEADS * DHEAD * CIN) {
        float s = 0.f;
        #pragma unroll 1
        for (int b = 0; b < BPH; b++) s += g_part_kvs[b][i];
        g_kvs[i] = s;
    }
    if (i < NHEADS * DHEAD) {
        float s = 0.f;
        for (int b = 0; b < BPH; b++) s += g_part_kss[b][i];
        g_kssum[i] = s;
    }
    if (i < CIN) {
        float s = 0.f;
        for (int b = 0; b < BPH; b++) s += g_part_cs[b][i];
        g_colsum[i] = s;
    }
}

// =====================================================================
// Phase B: q-projection (mma) + normalize + out GEMM (mma)
// smem floats: xsA 16640 | wt 16384 | kvs 16384 | qs 4352 | bias 64 |
//   kss 64 | cs 256 | red 256 | red2 256 | inv 64 | rno 64 = 54784 (219136 B)
// =====================================================================
__global__ __launch_bounds__(256, 1)
void phaseB_kernel(const float* __restrict__ x,
                   const float* __restrict__ Wq,
                   const float* __restrict__ bq,
                   float* __restrict__ out)
{
    const int h = blockIdx.y, tid = threadIdx.x;
    const int lane = tid & 31, w = tid >> 5;
    const int gq = lane >> 2, ct = lane & 3;

    float* xsA  = smf;             // [64][260]
    float* wt   = xsA + 16640;     // [256][64] swizzled
    float* kvs  = wt  + 16384;     // [64][256] swizzled: phys_c = c ^ (8*(m&3))
    float* qs   = kvs + 16384;     // [64][QS]
    float* bias = qs  + 4352;
    float* kss  = bias + 64;
    float* cs   = kss + 64;
    float* red  = cs  + 256;
    float* red2 = red + 256;
    float* inv  = red2 + 256;
    float* rno  = inv + 64;

    for (int i = tid; i < 16384; i += 256) {
        int c = i >> 6, m = i & 63;
        wt[c * 64 + (m ^ (8 * (c & 3)))] = rna(Wq[(h * 64 + m) * 256 + c]);
    }
    for (int i = tid; i < 16384; i += 256) {
        int m = i >> 8, c = i & 255;
        kvs[m * 256 + (c ^ (8 * (m & 3)))] = rna(g_kvs[h * 16384 + m * 256 + c]);
    }
    if (tid < 64) { bias[tid] = bq[h * 64 + tid]; kss[tid] = g_kssum[h * 64 + tid]; }
    if (tid < CIN) cs[tid] = g_colsum[tid];
    __syncthreads();

    const int ps = w >> 1, nh = w & 1;   // proj
    const int sn = w >> 1, ch = w & 1;   // out: 4 row-slabs x 2 c-halves

    for (int tile = blockIdx.x; tile < NT; tile += BPH) {
        const int base = tile * TILE;
        const int valid = (NNODES - base < TILE) ? (NNODES - base) : TILE;

        for (int i = tid; i < TILE * 64; i += 256) {
            int n = i >> 6, c4 = (i & 63) << 2;
            float4 v = make_float4(0.f, 0.f, 0.f, 0.f);
            if (n < valid) v = *(const float4*)(x + (size_t)(base + n) * CIN + c4);
            *(float4*)(xsA + n * XS + c4) =
                make_float4(rna(v.x), rna(v.y), rna(v.z), rna(v.w));
        }
        __syncthreads();

        // ---- q projection
        {
            float pc[4][4];
            #pragma unroll
            for (int t = 0; t < 4; t++) { pc[t][0]=0.f; pc[t][1]=0.f; pc[t][2]=0.f; pc[t][3]=0.f; }
            #pragma unroll 4
            for (int kb = 0; kb < 32; kb++) {
                const float* xr = xsA + (ps * 16 + gq) * XS + kb * 8 + ct;
                uint4 a;
                a.x = fu(xr[0]); a.y = fu(xr[8 * XS]);
                a.z = fu(xr[4]); a.w = fu(xr[8 * XS + 4]);
                #pragma unroll
                for (int t = 0; t < 4; t++) {
                    int nt = nh * 4 + t;
                    const float* wp = wt + (kb * 8 + ct) * 64 + ((nt * 8 + gq) ^ (8 * ct));
                    uint2 b; b.x = fu(wp[0]); b.y = fu(wp[4 * 64]);
                    mma8(pc[t], a, b);
                }
            }
            int r0 = ps * 16 + gq;
            #pragma unroll
            for (int t = 0; t < 4; t++) {
                int cb = (nh * 4 + t) * 8 + 2 * ct;
                float b0 = bias[cb], b1 = bias[cb + 1];
                *(float2*)(qs + r0 * QS + cb)       = make_float2(pc[t][0] + b0, pc[t][1] + b1);
                *(float2*)(qs + (r0 + 8) * QS + cb) = make_float2(pc[t][2] + b0, pc[t][3] + b1);
            }
        }
        __syncthreads();

        // ---- norms + dot(P, ks_sum)
        {
            int n = tid >> 2, q = tid & 3;
            const float* qr = qs + n * QS + q * 16;
            const float* kr = kss + q * 16;
            float s = 0.f, d = 0.f;
            #pragma unroll
            for (int i2 = 0; i2 < 16; i2++) { float v = qr[i2]; s += v * v; d += v * kr[i2]; }
            red[n * 4 + q] = s; red2[n * 4 + q] = d;
        }
        __syncthreads();
        if (tid < 64) {
            float s = red [tid*4] + red [tid*4+1] + red [tid*4+2] + red [tid*4+3];
            float d = red2[tid*4] + red2[tid*4+1] + red2[tid*4+2] + red2[tid*4+3];
            float iv = rsqrtf(s);
            inv[tid] = iv;
            rno[tid] = 1.0f / (iv * d + (float)NNODES);
        }
        __syncthreads();
        for (int i = tid; i < TILE * 64; i += 256) {
            int n = i >> 6, m = i & 63;
            qs[n * QS + m] = rna(qs[n * QS + m] * inv[n]);
        }
        __syncthreads();

        // ---- out = (qs @ kvs + colsum) * rno
        {
            float oc[16][4];
            #pragma unroll
            for (int t = 0; t < 16; t++) { oc[t][0]=0.f; oc[t][1]=0.f; oc[t][2]=0.f; oc[t][3]=0.f; }
            #pragma unroll
            for (int kb = 0; kb < 8; kb++) {
                const float* ap = qs + (sn * 16 + gq) * QS + kb * 8 + ct;
                uint4 a;
                a.x = fu(ap[0]); a.y = fu(ap[8 * QS]);
                a.z = fu(ap[4]); a.w = fu(ap[8 * QS + 4]);
                const float* kp0 = kvs + (kb * 8 + ct) * 256;
                const float* kp1 = kvs + (kb * 8 + ct + 4) * 256;
                const int sw = 8 * ct;
                #pragma unroll
                for (int t = 0; t < 16; t++) {
                    int c = ch * 128 + t * 8 + gq;
                    uint2 b; b.x = fu(kp0[c ^ sw]); b.y = fu(kp1[c ^ sw]);
                    mma8(oc[t], a, b);
                }
            }
            int n0 = sn * 16 + gq;
            float r0v = rno[n0], r1v = rno[n0 + 8];
            #pragma unroll
            for (int t = 0; t < 16; t++) {
                int c0 = ch * 128 + t * 8 + 2 * ct;
                float cv0 = cs[c0], cv1 = cs[c0 + 1];
                if (n0 < valid)
                    *(float2*)(out + (size_t)(base + n0) * (NHEADS * CIN) + h * CIN + c0) =
                        make_float2((oc[t][0] + cv0) * r0v, (oc[t][1] + cv1) * r0v);
                if (n0 + 8 < valid)
                    *(float2*)(out + (size_t)(base + n0 + 8) * (NHEADS * CIN) + h * CIN + c0) =
                        make_float2((oc[t][2] + cv0) * r1v, (oc[t][3] + cv1) * r1v);
            }
        }
        __syncthreads();
    }
}

// =====================================================================
extern "C" void kernel_launch(void* const* d_in, const int* in_sizes, int n_in,
                              void* d_out, int out_size)
{
    const float* x    = (const float*)d_in[0];
    const float* Wq_w = (const float*)d_in[1];
    const float* Wq_b = (const float*)d_in[2];
    const float* Wk_w = (const float*)d_in[3];
    const float* Wk_b = (const float*)d_in[4];
    float* out = (float*)d_out;

    const int smemA = 55488 * (int)sizeof(float);   // 221952 B
    const int smemB = 54784 * (int)sizeof(float);   // 219136 B

    cudaFuncSetAttribute(phaseA_kernel, cudaFuncAttributeMaxDynamicSharedMemorySize, smemA);
    cudaFuncSetAttribute(phaseB_kernel, cudaFuncAttributeMaxDynamicSharedMemorySize, smemB);

    phaseA_kernel<<<dim3(BPH, NHEADS), 256, smemA>>>(x, Wk_w, Wk_b);
    reduce_kernel<<<256, 256>>>();
    phaseB_kernel<<<dim3(BPH, NHEADS), 256, smemB>>>(x, Wq_w, Wq_b, out);
}

// round 7
// speedup vs baseline: 2.7072x; 1.1360x over previous
#include <cuda_runtime.h>
#include <math.h>
#include <stdint.h>

#define NNODES 100000
#define CIN    256
#define NHEADS 4
#define DHEAD  64
#define BPH    37
#define TILE   64
#define NT     ((NNODES + TILE - 1) / TILE)   // 1563
#define XS     260                            // xsA stride (A-frag clean)
#define KS     72                             // ks stride  (transposed-A clean)
#define QS     68                             // qs stride  (A-frag clean)
#define NTHR   512

// ---------------- helpers ----------------
__device__ __forceinline__ float rna(float f) {
    unsigned int u;
    asm("cvt.rna.tf32.f32 %0, %1;" : "=r"(u) : "f"(f));
    return __uint_as_float(u);
}
__device__ __forceinline__ unsigned int fu(float f) { return __float_as_uint(f); }
__device__ __forceinline__ void mma8(float c[4], uint4 a, uint2 b) {
    asm volatile("mma.sync.aligned.m16n8k8.row.col.f32.tf32.tf32.f32 "
        "{%0,%1,%2,%3}, {%4,%5,%6,%7}, {%8,%9}, {%0,%1,%2,%3};"
        : "+f"(c[0]), "+f"(c[1]), "+f"(c[2]), "+f"(c[3])
        : "r"(a.x), "r"(a.y), "r"(a.z), "r"(a.w), "r"(b.x), "r"(b.y));
}

// ---------------- device scratch ----------------
__device__ float g_part_kvs[BPH][NHEADS * DHEAD * CIN];
__device__ float g_part_kss[BPH][NHEADS * DHEAD];
__device__ float g_part_cs [BPH][CIN];
__device__ float g_kvs   [NHEADS * DHEAD * CIN];
__device__ float g_kssum [NHEADS * DHEAD];
__device__ float g_colsum[CIN];

extern __shared__ float smf[];

// =====================================================================
// Phase A: k-projection (mma) + normalize + kv (mma, reg-resident C)
// smem floats: xsA 16640 | xsB 16384 | wt 16384 | ks 4608 | bias 64 |
//   kss 64 | red 512 | inv 64 | csred 2048  = 56768 (227072 B)
// =====================================================================
__global__ __launch_bounds__(NTHR, 1)
void phaseA_kernel(const float* __restrict__ x,
                   const float* __restrict__ Wk,
                   const float* __restrict__ bk)
{
    const int h = blockIdx.y, bx = blockIdx.x, tid = threadIdx.x;
    const int lane = tid & 31, w = tid >> 5;
    const int gq = lane >> 2, ct = lane & 3;

    float* xsA  = smf;             // [64][260]
    float* xsB  = xsA + 16640;     // [64][256] swizzled: phys_c = c ^ (8*(n&3))
    float* wt   = xsB + 16384;     // [256][64] swizzled: phys_m = m ^ (8*(c&3))
    float* ks   = wt  + 16384;     // [64][KS]
    float* bias = ks  + 4608;
    float* kss  = bias + 64;
    float* red  = kss + 64;        // [512]
    float* inv  = red + 512;       // [64]
    float* csred= inv + 64;        // [256][8]

    for (int i = tid; i < 16384; i += NTHR) {
        int c = i >> 6, m = i & 63;
        wt[c * 64 + (m ^ (8 * (c & 3)))] = rna(Wk[(h * 64 + m) * 256 + c]);
    }
    if (tid < 64) { bias[tid] = bk[h * 64 + tid]; kss[tid] = 0.f; }

    const int ps = w >> 2, nq = w & 3;   // proj: 4 row-slabs x 4 n-quarters
    const int km = w >> 2, cq = w & 3;   // kv:   4 m-slabs  x 4 c-quarters

    float kvC[8][4];
    #pragma unroll
    for (int t = 0; t < 8; t++) { kvC[t][0]=0.f; kvC[t][1]=0.f; kvC[t][2]=0.f; kvC[t][3]=0.f; }
    float4 csacc = make_float4(0.f, 0.f, 0.f, 0.f);

    // prefetch first tile
    float4 pf[8];
    {
        const int base = bx * TILE;
        const int valid = (NNODES - base < TILE) ? (NNODES - base) : TILE;
        #pragma unroll
        for (int j = 0; j < 8; j++) {
            int i = tid + j * NTHR;
            int n = i >> 6, c4 = (i & 63) << 2;
            pf[j] = (n < valid) ? *(const float4*)(x + (size_t)(base + n) * CIN + c4)
                                : make_float4(0.f, 0.f, 0.f, 0.f);
        }
    }
    __syncthreads();

    for (int tile = bx; tile < NT; tile += BPH) {
        // ---- store prefetched tile (both copies) + exact colsum partials
        #pragma unroll
        for (int j = 0; j < 8; j++) {
            int i = tid + j * NTHR;
            int n = i >> 6, c4 = (i & 63) << 2;
            float4 v = pf[j];
            csacc.x += v.x; csacc.y += v.y; csacc.z += v.z; csacc.w += v.w;
            float4 r = make_float4(rna(v.x), rna(v.y), rna(v.z), rna(v.w));
            *(float4*)(xsA + n * XS + c4) = r;
            *(float4*)(xsB + n * 256 + (c4 ^ (8 * (n & 3)))) = r;
        }
        __syncthreads();

        // ---- prefetch next tile (overlaps with mma work below)
        if (tile + BPH < NT) {
            const int nb = (tile + BPH) * TILE;
            const int nv = (NNODES - nb < TILE) ? (NNODES - nb) : TILE;
            #pragma unroll
            for (int j = 0; j < 8; j++) {
                int i = tid + j * NTHR;
                int n = i >> 6, c4 = (i & 63) << 2;
                pf[j] = (n < nv) ? *(const float4*)(x + (size_t)(nb + n) * CIN + c4)
                                 : make_float4(0.f, 0.f, 0.f, 0.f);
            }
        }

        const int base = tile * TILE;
        const int valid = (NNODES - base < TILE) ? (NNODES - base) : TILE;

        // ---- k projection: P[64][64] = X @ WkT (per warp 16 rows x 16 cols)
        {
            float pc[2][4];
            pc[0][0]=0.f; pc[0][1]=0.f; pc[0][2]=0.f; pc[0][3]=0.f;
            pc[1][0]=0.f; pc[1][1]=0.f; pc[1][2]=0.f; pc[1][3]=0.f;
            #pragma unroll 4
            for (int kb = 0; kb < 32; kb++) {
                const float* xr = xsA + (ps * 16 + gq) * XS + kb * 8 + ct;
                uint4 a;
                a.x = fu(xr[0]); a.y = fu(xr[8 * XS]);
                a.z = fu(xr[4]); a.w = fu(xr[8 * XS + 4]);
                #pragma unroll
                for (int t = 0; t < 2; t++) {
                    int nt = nq * 2 + t;
                    const float* wp = wt + (kb * 8 + ct) * 64 + ((nt * 8 + gq) ^ (8 * ct));
                    uint2 b; b.x = fu(wp[0]); b.y = fu(wp[4 * 64]);
                    mma8(pc[t], a, b);
                }
            }
            int r0 = ps * 16 + gq;
            #pragma unroll
            for (int t = 0; t < 2; t++) {
                int cb = (nq * 2 + t) * 8 + 2 * ct;
                float b0 = bias[cb], b1 = bias[cb + 1];
                *(float2*)(ks + r0 * KS + cb)       = make_float2(pc[t][0] + b0, pc[t][1] + b1);
                *(float2*)(ks + (r0 + 8) * KS + cb) = make_float2(pc[t][2] + b0, pc[t][3] + b1);
            }
        }
        __syncthreads();

        // ---- row norms (8 threads per row)
        {
            int n = tid >> 3, q8 = tid & 7;
            const float* kr = ks + n * KS + q8 * 8;
            float s = 0.f;
            #pragma unroll
            for (int i2 = 0; i2 < 8; i2++) { float v = kr[i2]; s += v * v; }
            red[n * 8 + q8] = s;
        }
        __syncthreads();
        if (tid < 64) {
            float s = 0.f;
            #pragma unroll
            for (int j = 0; j < 8; j++) s += red[tid * 8 + j];
            inv[tid] = (tid < valid) ? rsqrtf(s) : 0.f;
        }
        __syncthreads();
        // ---- normalize + tf32-round in place
        for (int i = tid; i < TILE * 64; i += NTHR) {
            int n = i >> 6, m = i & 63;
            ks[n * KS + m] = rna(ks[n * KS + m] * inv[n]);
        }
        __syncthreads();
        // ---- ks_sum partials (8 row-groups)
        {
            int m = tid & 63, rg = tid >> 6;
            float s = 0.f;
            #pragma unroll
            for (int r = 0; r < 8; r++) s += ks[(rg * 8 + r) * KS + m];
            red[rg * 64 + m] = s;
        }
        __syncthreads();
        if (tid < 64) {
            float s = 0.f;
            #pragma unroll
            for (int j = 0; j < 8; j++) s += red[j * 64 + tid];
            kss[tid] += s;
        }

        // ---- kv += ks^T @ x  (per warp 16 m x 64 c)
        {
            #pragma unroll
            for (int kb = 0; kb < 8; kb++) {
                const float* kp = ks + (kb * 8 + ct) * KS + km * 16 + gq;
                uint4 a;
                a.x = fu(kp[0]); a.y = fu(kp[8]);
                a.z = fu(kp[4 * KS]); a.w = fu(kp[4 * KS + 8]);
                const float* xb0 = xsB + (kb * 8 + ct) * 256;
                const float* xb1 = xsB + (kb * 8 + ct + 4) * 256;
                const int sw = 8 * ct;
                #pragma unroll
                for (int t = 0; t < 8; t++) {
                    int c = cq * 64 + t * 8 + gq;
                    uint2 b; b.x = fu(xb0[c ^ sw]); b.y = fu(xb1[c ^ sw]);
                    mma8(kvC[t], a, b);
                }
            }
        }
        __syncthreads();
    }

    // ---- deterministic per-block partials
    {
        float* dst = g_part_kvs[bx] + h * (DHEAD * CIN);
        #pragma unroll
        for (int t = 0; t < 8; t++) {
            int c0 = cq * 64 + t * 8 + 2 * ct;
            int m0 = km * 16 + gq;
            dst[m0 * 256 + c0]           = kvC[t][0];
            dst[m0 * 256 + c0 + 1]       = kvC[t][1];
            dst[(m0 + 8) * 256 + c0]     = kvC[t][2];
            dst[(m0 + 8) * 256 + c0 + 1] = kvC[t][3];
        }
    }
    if (tid < 64) g_part_kss[bx][h * 64 + tid] = kss[tid];
    {
        int c4 = (tid & 63) * 4, grp = tid >> 6;
        csred[(c4+0)*8+grp] = csacc.x; csred[(c4+1)*8+grp] = csacc.y;
        csred[(c4+2)*8+grp] = csacc.z; csred[(c4+3)*8+grp] = csacc.w;
    }
    __syncthreads();
    if (h == 0 && tid < CIN) {
        float s = 0.f;
        #pragma unroll
        for (int j = 0; j < 8; j++) s += csred[tid * 8 + j];
        g_part_cs[bx][tid] = s;
    }
}

// =====================================================================
// Reduce: fixed-order partial sums
// =====================================================================
__global__ void reduce_kernel()
{
    int i = blockIdx.x * 256 + threadIdx.x;
    if (i < NHEADS * DHEAD * CIN) {
        float s = 0.f;
        #pragma unroll 1
        for (int b = 0; b < BPH; b++) s += g_part_kvs[b][i];
        g_kvs[i] = s;
    }
    if (i < NHEADS * DHEAD) {
        float s = 0.f;
        for (int b = 0; b < BPH; b++) s += g_part_kss[b][i];
        g_kssum[i] = s;
    }
    if (i < CIN) {
        float s = 0.f;
        for (int b = 0; b < BPH; b++) s += g_part_cs[b][i];
        g_colsum[i] = s;
    }
}

// =====================================================================
// Phase B: q-projection (mma) + normalize + out GEMM (mma)
// smem floats: xsA 16640 | wt 16384 | kvs 16384 | qs 4352 | bias 64 |
//   kss 64 | cs 256 | red 512 | red2 512 | inv 64 | rno 64 = 55296 (221184 B)
// =====================================================================
__global__ __launch_bounds__(NTHR, 1)
void phaseB_kernel(const float* __restrict__ x,
                   const float* __restrict__ Wq,
                   const float* __restrict__ bq,
                   float* __restrict__ out)
{
    const int h = blockIdx.y, tid = threadIdx.x;
    const int lane = tid & 31, w = tid >> 5;
    const int gq = lane >> 2, ct = lane & 3;

    float* xsA  = smf;             // [64][260]
    float* wt   = xsA + 16640;     // [256][64] swizzled
    float* kvs  = wt  + 16384;     // [64][256] swizzled: phys_c = c ^ (8*(m&3))
    float* qs   = kvs + 16384;     // [64][QS]
    float* bias = qs  + 4352;
    float* kss  = bias + 64;
    float* cs   = kss + 64;
    float* red  = cs  + 256;       // [512]
    float* red2 = red + 512;       // [512]
    float* inv  = red2 + 512;      // [64]
    float* rno  = inv + 64;        // [64]

    for (int i = tid; i < 16384; i += NTHR) {
        int c = i >> 6, m = i & 63;
        wt[c * 64 + (m ^ (8 * (c & 3)))] = rna(Wq[(h * 64 + m) * 256 + c]);
    }
    for (int i = tid; i < 16384; i += NTHR) {
        int m = i >> 8, c = i & 255;
        kvs[m * 256 + (c ^ (8 * (m & 3)))] = rna(g_kvs[h * 16384 + m * 256 + c]);
    }
    if (tid < 64) { bias[tid] = bq[h * 64 + tid]; kss[tid] = g_kssum[h * 64 + tid]; }
    if (tid < CIN) cs[tid] = g_colsum[tid];

    const int ps = w >> 2, nq = w & 3;   // proj
    const int sn = w >> 2, cq = w & 3;   // out: 4 row-slabs x 4 c-quarters

    // prefetch first tile
    float4 pf[8];
    {
        const int base = blockIdx.x * TILE;
        const int valid = (NNODES - base < TILE) ? (NNODES - base) : TILE;
        #pragma unroll
        for (int j = 0; j < 8; j++) {
            int i = tid + j * NTHR;
            int n = i >> 6, c4 = (i & 63) << 2;
            pf[j] = (n < valid) ? *(const float4*)(x + (size_t)(base + n) * CIN + c4)
                                : make_float4(0.f, 0.f, 0.f, 0.f);
        }
    }
    __syncthreads();

    for (int tile = blockIdx.x; tile < NT; tile += BPH) {
        #pragma unroll
        for (int j = 0; j < 8; j++) {
            int i = tid + j * NTHR;
            int n = i >> 6, c4 = (i & 63) << 2;
            float4 v = pf[j];
            *(float4*)(xsA + n * XS + c4) =
                make_float4(rna(v.x), rna(v.y), rna(v.z), rna(v.w));
        }
        __syncthreads();

        if (tile + BPH < NT) {
            const int nb = (tile + BPH) * TILE;
            const int nv = (NNODES - nb < TILE) ? (NNODES - nb) : TILE;
            #pragma unroll
            for (int j = 0; j < 8; j++) {
                int i = tid + j * NTHR;
                int n = i >> 6, c4 = (i & 63) << 2;
                pf[j] = (n < nv) ? *(const float4*)(x + (size_t)(nb + n) * CIN + c4)
                                 : make_float4(0.f, 0.f, 0.f, 0.f);
            }
        }

        const int base = tile * TILE;
        const int valid = (NNODES - base < TILE) ? (NNODES - base) : TILE;

        // ---- q projection
        {
            float pc[2][4];
            pc[0][0]=0.f; pc[0][1]=0.f; pc[0][2]=0.f; pc[0][3]=0.f;
            pc[1][0]=0.f; pc[1][1]=0.f; pc[1][2]=0.f; pc[1][3]=0.f;
            #pragma unroll 4
            for (int kb = 0; kb < 32; kb++) {
                const float* xr = xsA + (ps * 16 + gq) * XS + kb * 8 + ct;
                uint4 a;
                a.x = fu(xr[0]); a.y = fu(xr[8 * XS]);
                a.z = fu(xr[4]); a.w = fu(xr[8 * XS + 4]);
                #pragma unroll
                for (int t = 0; t < 2; t++) {
                    int nt = nq * 2 + t;
                    const float* wp = wt + (kb * 8 + ct) * 64 + ((nt * 8 + gq) ^ (8 * ct));
                    uint2 b; b.x = fu(wp[0]); b.y = fu(wp[4 * 64]);
                    mma8(pc[t], a, b);
                }
            }
            int r0 = ps * 16 + gq;
            #pragma unroll
            for (int t = 0; t < 2; t++) {
                int cb = (nq * 2 + t) * 8 + 2 * ct;
                float b0 = bias[cb], b1 = bias[cb + 1];
                *(float2*)(qs + r0 * QS + cb)       = make_float2(pc[t][0] + b0, pc[t][1] + b1);
                *(float2*)(qs + (r0 + 8) * QS + cb) = make_float2(pc[t][2] + b0, pc[t][3] + b1);
            }
        }
        __syncthreads();

        // ---- norms + dot(P, ks_sum)
        {
            int n = tid >> 3, q8 = tid & 7;
            const float* qr = qs + n * QS + q8 * 8;
            const float* kr = kss + q8 * 8;
            float s = 0.f, d = 0.f;
            #pragma unroll
            for (int i2 = 0; i2 < 8; i2++) { float v = qr[i2]; s += v * v; d += v * kr[i2]; }
            red[n * 8 + q8] = s; red2[n * 8 + q8] = d;
        }
        __syncthreads();
        if (tid < 64) {
            float s = 0.f, d = 0.f;
            #pragma unroll
            for (int j = 0; j < 8; j++) { s += red[tid*8+j]; d += red2[tid*8+j]; }
            float iv = rsqrtf(s);
            inv[tid] = iv;
            rno[tid] = 1.0f / (iv * d + (float)NNODES);
        }
        __syncthreads();
        for (int i = tid; i < TILE * 64; i += NTHR) {
            int n = i >> 6, m = i & 63;
            qs[n * QS + m] = rna(qs[n * QS + m] * inv[n]);
        }
        __syncthreads();

        // ---- out = (qs @ kvs + colsum) * rno (per warp 16 rows x 64 cols)
        {
            float oc[8][4];
            #pragma unroll
            for (int t = 0; t < 8; t++) { oc[t][0]=0.f; oc[t][1]=0.f; oc[t][2]=0.f; oc[t][3]=0.f; }
            #pragma unroll
            for (int kb = 0; kb < 8; kb++) {
                const float* ap = qs + (sn * 16 + gq) * QS + kb * 8 + ct;
                uint4 a;
                a.x = fu(ap[0]); a.y = fu(ap[8 * QS]);
                a.z = fu(ap[4]); a.w = fu(ap[8 * QS + 4]);
                const float* kp0 = kvs + (kb * 8 + ct) * 256;
                const float* kp1 = kvs + (kb * 8 + ct + 4) * 256;
                const int sw = 8 * ct;
                #pragma unroll
                for (int t = 0; t < 8; t++) {
                    int c = cq * 64 + t * 8 + gq;
                    uint2 b; b.x = fu(kp0[c ^ sw]); b.y = fu(kp1[c ^ sw]);
                    mma8(oc[t], a, b);
                }
            }
            int n0 = sn * 16 + gq;
            float r0v = rno[n0], r1v = rno[n0 + 8];
            #pragma unroll
            for (int t = 0; t < 8; t++) {
                int c0 = cq * 64 + t * 8 + 2 * ct;
                float cv0 = cs[c0], cv1 = cs[c0 + 1];
                if (n0 < valid)
                    *(float2*)(out + (size_t)(base + n0) * (NHEADS * CIN) + h * CIN + c0) =
                        make_float2((oc[t][0] + cv0) * r0v, (oc[t][1] + cv1) * r0v);
                if (n0 + 8 < valid)
                    *(float2*)(out + (size_t)(base + n0 + 8) * (NHEADS * CIN) + h * CIN + c0) =
                        make_float2((oc[t][2] + cv0) * r1v, (oc[t][3] + cv1) * r1v);
            }
        }
        __syncthreads();
    }
}

// =====================================================================
extern "C" void kernel_launch(void* const* d_in, const int* in_sizes, int n_in,
                              void* d_out, int out_size)
{
    const float* x    = (const float*)d_in[0];
    const float* Wq_w = (const float*)d_in[1];
    const float* Wq_b = (const float*)d_in[2];
    const float* Wk_w = (const float*)d_in[3];
    const float* Wk_b = (const float*)d_in[4];
    float* out = (float*)d_out;

    const int smemA = 56768 * (int)sizeof(float);   // 227072 B
    const int smemB = 55296 * (int)sizeof(float);   // 221184 B

    cudaFuncSetAttribute(phaseA_kernel, cudaFuncAttributeMaxDynamicSharedMemorySize, smemA);
    cudaFuncSetAttribute(phaseB_kernel, cudaFuncAttributeMaxDynamicSharedMemorySize, smemB);

    phaseA_kernel<<<dim3(BPH, NHEADS), NTHR, smemA>>>(x, Wk_w, Wk_b);
    reduce_kernel<<<256, 256>>>();
    phaseB_kernel<<<dim3(BPH, NHEADS), NTHR, smemB>>>(x, Wq_w, Wq_b, out);
}

// round 8
// speedup vs baseline: 2.7741x; 1.0247x over previous
#include <cuda_runtime.h>
#include <math.h>
#include <stdint.h>

#define NNODES 100000
#define CIN    256
#define NHEADS 4
#define DHEAD  64
#define BPH    37
#define TILE   64
#define NT     ((NNODES + TILE - 1) / TILE)   // 1563
#define XS     260                            // xsA stride (A-frag clean)
#define KS     72                             // ks stride  (transposed-A clean)
#define QS     68                             // qs stride  (A-frag clean)
#define NTHR   512

// ---------------- helpers ----------------
__device__ __forceinline__ float rna(float f) {
    unsigned int u;
    asm("cvt.rna.tf32.f32 %0, %1;" : "=r"(u) : "f"(f));
    return __uint_as_float(u);
}
__device__ __forceinline__ unsigned int fu(float f) { return __float_as_uint(f); }
__device__ __forceinline__ void mma8(float c[4], uint4 a, uint2 b) {
    asm volatile("mma.sync.aligned.m16n8k8.row.col.f32.tf32.tf32.f32 "
        "{%0,%1,%2,%3}, {%4,%5,%6,%7}, {%8,%9}, {%0,%1,%2,%3};"
        : "+f"(c[0]), "+f"(c[1]), "+f"(c[2]), "+f"(c[3])
        : "r"(a.x), "r"(a.y), "r"(a.z), "r"(a.w), "r"(b.x), "r"(b.y));
}

// ---------------- device scratch ----------------
__device__ float g_part_kvs[BPH][NHEADS * DHEAD * CIN];
__device__ float g_part_kss[BPH][NHEADS * DHEAD];
__device__ float g_part_cs [BPH][CIN];
__device__ float g_kvs   [NHEADS * DHEAD * CIN];
__device__ float g_kssum [NHEADS * DHEAD];
__device__ float g_colsum[CIN];

extern __shared__ float smf[];

// =====================================================================
// Phase A
// smem floats: xsA 16640 | xsB 16384 | wt 16384 | ks 4608 | bias 64 |
//   kss 64 | red 512 | inv 64 | csred 2048  = 56768 (227072 B)
// =====================================================================
__global__ __launch_bounds__(NTHR, 1)
void phaseA_kernel(const float* __restrict__ x,
                   const float* __restrict__ Wk,
                   const float* __restrict__ bk)
{
    const int h = blockIdx.y, bx = blockIdx.x, tid = threadIdx.x;
    const int lane = tid & 31, w = tid >> 5;
    const int gq = lane >> 2, ct = lane & 3;

    float* xsA  = smf;             // [64][260]
    float* xsB  = xsA + 16640;     // [64][256] swizzled: phys_c = c ^ (8*(n&3))
    float* wt   = xsB + 16384;     // [256][64] swizzled: phys_m = m ^ (8*(c&3))
    float* ks   = wt  + 16384;     // [64][KS]
    float* bias = ks  + 4608;
    float* kss  = bias + 64;
    float* red  = kss + 64;        // [512]
    float* inv  = red + 512;       // [64]
    float* csred= inv + 64;        // [256][8]

    for (int i = tid; i < 16384; i += NTHR) {
        int c = i >> 6, m = i & 63;
        wt[c * 64 + (m ^ (8 * (c & 3)))] = rna(Wk[(h * 64 + m) * 256 + c]);
    }
    if (tid < 64) { bias[tid] = bk[h * 64 + tid]; kss[tid] = 0.f; }

    const int ps = w >> 2, nq = w & 3;   // proj: 4 row-slabs x 4 n-quarters
    const int km = w >> 2, cq = w & 3;   // kv:   4 m-slabs  x 4 c-quarters

    float kvC[8][4];
    #pragma unroll
    for (int t = 0; t < 8; t++) { kvC[t][0]=0.f; kvC[t][1]=0.f; kvC[t][2]=0.f; kvC[t][3]=0.f; }
    float4 csacc = make_float4(0.f, 0.f, 0.f, 0.f);

    float4 pf[8];
    {
        const int base = bx * TILE;
        const int valid = (NNODES - base < TILE) ? (NNODES - base) : TILE;
        #pragma unroll
        for (int j = 0; j < 8; j++) {
            int i = tid + j * NTHR;
            int n = i >> 6, c4 = (i & 63) << 2;
            pf[j] = (n < valid) ? *(const float4*)(x + (size_t)(base + n) * CIN + c4)
                                : make_float4(0.f, 0.f, 0.f, 0.f);
        }
    }
    __syncthreads();

    for (int tile = bx; tile < NT; tile += BPH) {
        // ---- store prefetched tile (both copies) + colsum partials
        #pragma unroll
        for (int j = 0; j < 8; j++) {
            int i = tid + j * NTHR;
            int n = i >> 6, c4 = (i & 63) << 2;
            float4 v = pf[j];
            csacc.x += v.x; csacc.y += v.y; csacc.z += v.z; csacc.w += v.w;
            float4 r = make_float4(rna(v.x), rna(v.y), rna(v.z), rna(v.w));
            *(float4*)(xsA + n * XS + c4) = r;
            *(float4*)(xsB + n * 256 + (c4 ^ (8 * (n & 3)))) = r;
        }
        __syncthreads();

        // ---- prefetch next tile
        if (tile + BPH < NT) {
            const int nb = (tile + BPH) * TILE;
            const int nv = (NNODES - nb < TILE) ? (NNODES - nb) : TILE;
            #pragma unroll
            for (int j = 0; j < 8; j++) {
                int i = tid + j * NTHR;
                int n = i >> 6, c4 = (i & 63) << 2;
                pf[j] = (n < nv) ? *(const float4*)(x + (size_t)(nb + n) * CIN + c4)
                                 : make_float4(0.f, 0.f, 0.f, 0.f);
            }
        }

        const int base = tile * TILE;
        const int valid = (NNODES - base < TILE) ? (NNODES - base) : TILE;

        // ---- k projection + fused row-norm partials
        {
            float pc[2][4];
            pc[0][0]=0.f; pc[0][1]=0.f; pc[0][2]=0.f; pc[0][3]=0.f;
            pc[1][0]=0.f; pc[1][1]=0.f; pc[1][2]=0.f; pc[1][3]=0.f;
            #pragma unroll 4
            for (int kb = 0; kb < 32; kb++) {
                const float* xr = xsA + (ps * 16 + gq) * XS + kb * 8 + ct;
                uint4 a;
                a.x = fu(xr[0]); a.y = fu(xr[8 * XS]);
                a.z = fu(xr[4]); a.w = fu(xr[8 * XS + 4]);
                #pragma unroll
                for (int t = 0; t < 2; t++) {
                    int nt = nq * 2 + t;
                    const float* wp = wt + (kb * 8 + ct) * 64 + ((nt * 8 + gq) ^ (8 * ct));
                    uint2 b; b.x = fu(wp[0]); b.y = fu(wp[4 * 64]);
                    mma8(pc[t], a, b);
                }
            }
            int r0 = ps * 16 + gq;
            float nrm0 = 0.f, nrm1 = 0.f;
            #pragma unroll
            for (int t = 0; t < 2; t++) {
                int cb = (nq * 2 + t) * 8 + 2 * ct;
                float b0 = bias[cb], b1 = bias[cb + 1];
                float v0 = pc[t][0] + b0, v1 = pc[t][1] + b1;
                float v2 = pc[t][2] + b0, v3 = pc[t][3] + b1;
                *(float2*)(ks + r0 * KS + cb)       = make_float2(v0, v1);
                *(float2*)(ks + (r0 + 8) * KS + cb) = make_float2(v2, v3);
                nrm0 += v0 * v0 + v1 * v1;
                nrm1 += v2 * v2 + v3 * v3;
            }
            nrm0 += __shfl_xor_sync(0xffffffffu, nrm0, 1);
            nrm0 += __shfl_xor_sync(0xffffffffu, nrm0, 2);
            nrm1 += __shfl_xor_sync(0xffffffffu, nrm1, 1);
            nrm1 += __shfl_xor_sync(0xffffffffu, nrm1, 2);
            if (ct == 0) {
                red[r0 * 4 + nq]       = nrm0;
                red[(r0 + 8) * 4 + nq] = nrm1;
            }
        }
        __syncthreads();

        if (tid < 64) {
            float s = red[tid*4] + red[tid*4+1] + red[tid*4+2] + red[tid*4+3];
            inv[tid] = (tid < valid) ? rsqrtf(s) : 0.f;
        }
        __syncthreads();

        // ---- merged normalize + ks_sum partials (single pass over ks)
        {
            int m = tid & 63, rg = tid >> 6;
            float s = 0.f;
            #pragma unroll
            for (int r = 0; r < 8; r++) {
                int n = rg * 8 + r;
                float v = rna(ks[n * KS + m] * inv[n]);
                ks[n * KS + m] = v;
                s += v;
            }
            red[rg * 64 + m] = s;
        }
        __syncthreads();
        if (tid < 64) {
            float s = 0.f;
            #pragma unroll
            for (int j = 0; j < 8; j++) s += red[j * 64 + tid];
            kss[tid] += s;
        }

        // ---- kv += ks^T @ x
        {
            #pragma unroll
            for (int kb = 0; kb < 8; kb++) {
                const float* kp = ks + (kb * 8 + ct) * KS + km * 16 + gq;
                uint4 a;
                a.x = fu(kp[0]); a.y = fu(kp[8]);
                a.z = fu(kp[4 * KS]); a.w = fu(kp[4 * KS + 8]);
                const float* xb0 = xsB + (kb * 8 + ct) * 256;
                const float* xb1 = xsB + (kb * 8 + ct + 4) * 256;
                const int sw = 8 * ct;
                #pragma unroll
                for (int t = 0; t < 8; t++) {
                    int c = cq * 64 + t * 8 + gq;
                    uint2 b; b.x = fu(xb0[c ^ sw]); b.y = fu(xb1[c ^ sw]);
                    mma8(kvC[t], a, b);
                }
            }
        }
        __syncthreads();
    }

    // ---- deterministic per-block partials
    {
        float* dst = g_part_kvs[bx] + h * (DHEAD * CIN);
        #pragma unroll
        for (int t = 0; t < 8; t++) {
            int c0 = cq * 64 + t * 8 + 2 * ct;
            int m0 = km * 16 + gq;
            dst[m0 * 256 + c0]           = kvC[t][0];
            dst[m0 * 256 + c0 + 1]       = kvC[t][1];
            dst[(m0 + 8) * 256 + c0]     = kvC[t][2];
            dst[(m0 + 8) * 256 + c0 + 1] = kvC[t][3];
        }
    }
    if (tid < 64) g_part_kss[bx][h * 64 + tid] = kss[tid];
    {
        int c4 = (tid & 63) * 4, grp = tid >> 6;
        csred[(c4+0)*8+grp] = csacc.x; csred[(c4+1)*8+grp] = csacc.y;
        csred[(c4+2)*8+grp] = csacc.z; csred[(c4+3)*8+grp] = csacc.w;
    }
    __syncthreads();
    if (h == 0 && tid < CIN) {
        float s = 0.f;
        #pragma unroll
        for (int j = 0; j < 8; j++) s += csred[tid * 8 + j];
        g_part_cs[bx][tid] = s;
    }
}

// =====================================================================
// Reduce
// =====================================================================
__global__ void reduce_kernel()
{
    int i = blockIdx.x * 256 + threadIdx.x;
    if (i < NHEADS * DHEAD * CIN) {
        float s = 0.f;
        #pragma unroll 1
        for (int b = 0; b < BPH; b++) s += g_part_kvs[b][i];
        g_kvs[i] = s;
    }
    if (i < NHEADS * DHEAD) {
        float s = 0.f;
        for (int b = 0; b < BPH; b++) s += g_part_kss[b][i];
        g_kssum[i] = s;
    }
    if (i < CIN) {
        float s = 0.f;
        for (int b = 0; b < BPH; b++) s += g_part_cs[b][i];
        g_colsum[i] = s;
    }
}

// =====================================================================
// Phase B
// smem floats: xsA 16640 | wt 16384 | kvs 16384 | qs 4352 | bias 64 |
//   kss 64 | cs 256 | red 256 | red2 256 | inv 64 | rno 64 = 54784
// =====================================================================
__global__ __launch_bounds__(NTHR, 1)
void phaseB_kernel(const float* __restrict__ x,
                   const float* __restrict__ Wq,
                   const float* __restrict__ bq,
                   float* __restrict__ out)
{
    const int h = blockIdx.y, tid = threadIdx.x;
    const int lane = tid & 31, w = tid >> 5;
    const int gq = lane >> 2, ct = lane & 3;

    float* xsA  = smf;             // [64][260]
    float* wt   = xsA + 16640;     // [256][64] swizzled
    float* kvs  = wt  + 16384;     // [64][256] swizzled: phys_c = c ^ (8*(m&3))
    float* qs   = kvs + 16384;     // [64][QS]
    float* bias = qs  + 4352;
    float* kss  = bias + 64;
    float* cs   = kss + 64;
    float* red  = cs  + 256;       // [256]
    float* red2 = red + 256;       // [256]
    float* inv  = red2 + 256;      // [64]
    float* rno  = inv + 64;        // [64]

    for (int i = tid; i < 16384; i += NTHR) {
        int c = i >> 6, m = i & 63;
        wt[c * 64 + (m ^ (8 * (c & 3)))] = rna(Wq[(h * 64 + m) * 256 + c]);
    }
    for (int i = tid; i < 16384; i += NTHR) {
        int m = i >> 8, c = i & 255;
        kvs[m * 256 + (c ^ (8 * (m & 3)))] = rna(g_kvs[h * 16384 + m * 256 + c]);
    }
    if (tid < 64) { bias[tid] = bq[h * 64 + tid]; kss[tid] = g_kssum[h * 64 + tid]; }
    if (tid < CIN) cs[tid] = g_colsum[tid];

    const int ps = w >> 2, nq = w & 3;
    const int sn = w >> 2, cq = w & 3;

    float4 pf[8];
    {
        const int base = blockIdx.x * TILE;
        const int valid = (NNODES - base < TILE) ? (NNODES - base) : TILE;
        #pragma unroll
        for (int j = 0; j < 8; j++) {
            int i = tid + j * NTHR;
            int n = i >> 6, c4 = (i & 63) << 2;
            pf[j] = (n < valid) ? *(const float4*)(x + (size_t)(base + n) * CIN + c4)
                                : make_float4(0.f, 0.f, 0.f, 0.f);
        }
    }
    __syncthreads();

    for (int tile = blockIdx.x; tile < NT; tile += BPH) {
        #pragma unroll
        for (int j = 0; j < 8; j++) {
            int i = tid + j * NTHR;
            int n = i >> 6, c4 = (i & 63) << 2;
            float4 v = pf[j];
            *(float4*)(xsA + n * XS + c4) =
                make_float4(rna(v.x), rna(v.y), rna(v.z), rna(v.w));
        }
        __syncthreads();

        if (tile + BPH < NT) {
            const int nb = (tile + BPH) * TILE;
            const int nv = (NNODES - nb < TILE) ? (NNODES - nb) : TILE;
            #pragma unroll
            for (int j = 0; j < 8; j++) {
                int i = tid + j * NTHR;
                int n = i >> 6, c4 = (i & 63) << 2;
                pf[j] = (n < nv) ? *(const float4*)(x + (size_t)(nb + n) * CIN + c4)
                                 : make_float4(0.f, 0.f, 0.f, 0.f);
            }
        }

        const int base = tile * TILE;
        const int valid = (NNODES - base < TILE) ? (NNODES - base) : TILE;

        // ---- q projection + fused row-norm & ks_sum-dot partials
        {
            float pc[2][4];
            pc[0][0]=0.f; pc[0][1]=0.f; pc[0][2]=0.f; pc[0][3]=0.f;
            pc[1][0]=0.f; pc[1][1]=0.f; pc[1][2]=0.f; pc[1][3]=0.f;
            #pragma unroll 4
            for (int kb = 0; kb < 32; kb++) {
                const float* xr = xsA + (ps * 16 + gq) * XS + kb * 8 + ct;
                uint4 a;
                a.x = fu(xr[0]); a.y = fu(xr[8 * XS]);
                a.z = fu(xr[4]); a.w = fu(xr[8 * XS + 4]);
                #pragma unroll
                for (int t = 0; t < 2; t++) {
                    int nt = nq * 2 + t;
                    const float* wp = wt + (kb * 8 + ct) * 64 + ((nt * 8 + gq) ^ (8 * ct));
                    uint2 b; b.x = fu(wp[0]); b.y = fu(wp[4 * 64]);
                    mma8(pc[t], a, b);
                }
            }
            int r0 = ps * 16 + gq;
            float nrm0 = 0.f, nrm1 = 0.f, dot0 = 0.f, dot1 = 0.f;
            #pragma unroll
            for (int t = 0; t < 2; t++) {
                int cb = (nq * 2 + t) * 8 + 2 * ct;
                float b0 = bias[cb], b1 = bias[cb + 1];
                float k0 = kss[cb],  k1 = kss[cb + 1];
                float v0 = pc[t][0] + b0, v1 = pc[t][1] + b1;
                float v2 = pc[t][2] + b0, v3 = pc[t][3] + b1;
                *(float2*)(qs + r0 * QS + cb)       = make_float2(v0, v1);
                *(float2*)(qs + (r0 + 8) * QS + cb) = make_float2(v2, v3);
                nrm0 += v0 * v0 + v1 * v1;  dot0 += v0 * k0 + v1 * k1;
                nrm1 += v2 * v2 + v3 * v3;  dot1 += v2 * k0 + v3 * k1;
            }
            nrm0 += __shfl_xor_sync(0xffffffffu, nrm0, 1);
            nrm0 += __shfl_xor_sync(0xffffffffu, nrm0, 2);
            nrm1 += __shfl_xor_sync(0xffffffffu, nrm1, 1);
            nrm1 += __shfl_xor_sync(0xffffffffu, nrm1, 2);
            dot0 += __shfl_xor_sync(0xffffffffu, dot0, 1);
            dot0 += __shfl_xor_sync(0xffffffffu, dot0, 2);
            dot1 += __shfl_xor_sync(0xffffffffu, dot1, 1);
            dot1 += __shfl_xor_sync(0xffffffffu, dot1, 2);
            if (ct == 0) {
                red [r0 * 4 + nq] = nrm0;  red [(r0 + 8) * 4 + nq] = nrm1;
                red2[r0 * 4 + nq] = dot0;  red2[(r0 + 8) * 4 + nq] = dot1;
            }
        }
        __syncthreads();

        if (tid < 64) {
            float s = red [tid*4] + red [tid*4+1] + red [tid*4+2] + red [tid*4+3];
            float d = red2[tid*4] + red2[tid*4+1] + red2[tid*4+2] + red2[tid*4+3];
            float iv = rsqrtf(s);
            inv[tid] = iv;
            rno[tid] = 1.0f / (iv * d + (float)NNODES);
        }
        __syncthreads();
        for (int i = tid; i < TILE * 64; i += NTHR) {
            int n = i >> 6, m = i & 63;
            qs[n * QS + m] = rna(qs[n * QS + m] * inv[n]);
        }
        __syncthreads();

        // ---- out = (qs @ kvs + colsum) * rno
        {
            float oc[8][4];
            #pragma unroll
            for (int t = 0; t < 8; t++) { oc[t][0]=0.f; oc[t][1]=0.f; oc[t][2]=0.f; oc[t][3]=0.f; }
            #pragma unroll
            for (int kb = 0; kb < 8; kb++) {
                const float* ap = qs + (sn * 16 + gq) * QS + kb * 8 + ct;
                uint4 a;
                a.x = fu(ap[0]); a.y = fu(ap[8 * QS]);
                a.z = fu(ap[4]); a.w = fu(ap[8 * QS + 4]);
                const float* kp0 = kvs + (kb * 8 + ct) * 256;
                const float* kp1 = kvs + (kb * 8 + ct + 4) * 256;
                const int sw = 8 * ct;
                #pragma unroll
                for (int t = 0; t < 8; t++) {
                    int c = cq * 64 + t * 8 + gq;
                    uint2 b; b.x = fu(kp0[c ^ sw]); b.y = fu(kp1[c ^ sw]);
                    mma8(oc[t], a, b);
                }
            }
            int n0 = sn * 16 + gq;
            float r0v = rno[n0], r1v = rno[n0 + 8];
            #pragma unroll
            for (int t = 0; t < 8; t++) {
                int c0 = cq * 64 + t * 8 + 2 * ct;
                float cv0 = cs[c0], cv1 = cs[c0 + 1];
                if (n0 < valid)
                    *(float2*)(out + (size_t)(base + n0) * (NHEADS * CIN) + h * CIN + c0) =
                        make_float2((oc[t][0] + cv0) * r0v, (oc[t][1] + cv1) * r0v);
                if (n0 + 8 < valid)
                    *(float2*)(out + (size_t)(base + n0 + 8) * (NHEADS * CIN) + h * CIN + c0) =
                        make_float2((oc[t][2] + cv0) * r1v, (oc[t][3] + cv1) * r1v);
            }
        }
        __syncthreads();
    }
}

// =====================================================================
extern "C" void kernel_launch(void* const* d_in, const int* in_sizes, int n_in,
                              void* d_out, int out_size)
{
    const float* x    = (const float*)d_in[0];
    const float* Wq_w = (const float*)d_in[1];
    const float* Wq_b = (const float*)d_in[2];
    const float* Wk_w = (const float*)d_in[3];
    const float* Wk_b = (const float*)d_in[4];
    float* out = (float*)d_out;

    const int smemA = 56768 * (int)sizeof(float);   // 227072 B
    const int smemB = 54784 * (int)sizeof(float);   // 219136 B

    cudaFuncSetAttribute(phaseA_kernel, cudaFuncAttributeMaxDynamicSharedMemorySize, smemA);
    cudaFuncSetAttribute(phaseB_kernel, cudaFuncAttributeMaxDynamicSharedMemorySize, smemB);

    phaseA_kernel<<<dim3(BPH, NHEADS), NTHR, smemA>>>(x, Wk_w, Wk_b);
    reduce_kernel<<<256, 256>>>();
    phaseB_kernel<<<dim3(BPH, NHEADS), NTHR, smemB>>>(x, Wq_w, Wq_b, out);
}

// round 9
// speedup vs baseline: 3.0792x; 1.1100x over previous
#include <cuda_runtime.h>
#include <math.h>
#include <stdint.h>

#define NNODES 100000
#define CIN    256
#define NHEADS 4
#define DHEAD  64
#define BPH    37
#define TILE   64
#define NT     ((NNODES + TILE - 1) / TILE)   // 1563
#define XS     260                            // xsA stride (A-frag clean)
#define KS     72                             // ks stride  (transposed-A clean)
#define QS     68                             // qs stride  (A-frag clean)
#define NTHR   256

// ---------------- helpers ----------------
__device__ __forceinline__ float rna(float f) {
    unsigned int u;
    asm("cvt.rna.tf32.f32 %0, %1;" : "=r"(u) : "f"(f));
    return __uint_as_float(u);
}
__device__ __forceinline__ unsigned int fu(float f) { return __float_as_uint(f); }
__device__ __forceinline__ void mma8(float c[4], uint4 a, uint2 b) {
    asm volatile("mma.sync.aligned.m16n8k8.row.col.f32.tf32.tf32.f32 "
        "{%0,%1,%2,%3}, {%4,%5,%6,%7}, {%8,%9}, {%0,%1,%2,%3};"
        : "+f"(c[0]), "+f"(c[1]), "+f"(c[2]), "+f"(c[3])
        : "r"(a.x), "r"(a.y), "r"(a.z), "r"(a.w), "r"(b.x), "r"(b.y));
}

// ---------------- device scratch ----------------
__device__ float g_part_kvs[BPH][NHEADS * DHEAD * CIN];
__device__ float g_part_kss[BPH][NHEADS * DHEAD];
__device__ float g_part_cs [BPH][CIN];
__device__ float g_kvs   [NHEADS * DHEAD * CIN];
__device__ float g_kssum [NHEADS * DHEAD];
__device__ float g_colsum[CIN];

extern __shared__ float smf[];

// =====================================================================
// Phase A  (256 threads, 8 warps; proj warp-tile 16x32, kv warp-tile 32x64)
// smem floats: xsA 16640 | xsB 16384 | wt 16384 | ks 4608 | bias 64 |
//   kss 64 | red 512 | inv 64 | csred 1024  = 55744 (222976 B)
// =====================================================================
__global__ __launch_bounds__(NTHR, 1)
void phaseA_kernel(const float* __restrict__ x,
                   const float* __restrict__ Wk,
                   const float* __restrict__ bk)
{
    const int h = blockIdx.y, bx = blockIdx.x, tid = threadIdx.x;
    const int lane = tid & 31, w = tid >> 5;
    const int gq = lane >> 2, ct = lane & 3;

    float* xsA  = smf;             // [64][260]
    float* xsB  = xsA + 16640;     // [64][256] swizzled: phys_c = c ^ (8*(n&3))
    float* wt   = xsB + 16384;     // [256][64] swizzled: phys_m = m ^ (8*(c&3))
    float* ks   = wt  + 16384;     // [64][KS]
    float* bias = ks  + 4608;
    float* kss  = bias + 64;
    float* red  = kss + 64;        // [512]
    float* inv  = red + 512;       // [64]
    float* csred= inv + 64;        // [256][4]

    for (int i = tid; i < 16384; i += NTHR) {
        int c = i >> 6, m = i & 63;
        wt[c * 64 + (m ^ (8 * (c & 3)))] = rna(Wk[(h * 64 + m) * 256 + c]);
    }
    if (tid < 64) { bias[tid] = bk[h * 64 + tid]; kss[tid] = 0.f; }

    const int ps = w >> 1, nh = w & 1;   // proj: 4 row-slabs x 2 col-halves
    const int km = w >> 2, cq = w & 3;   // kv:   2 m-slabs(32) x 4 c-quarters(64)

    float kvC[2][8][4];
    #pragma unroll
    for (int mi = 0; mi < 2; mi++)
        #pragma unroll
        for (int t = 0; t < 8; t++) {
            kvC[mi][t][0]=0.f; kvC[mi][t][1]=0.f; kvC[mi][t][2]=0.f; kvC[mi][t][3]=0.f;
        }
    float4 csacc = make_float4(0.f, 0.f, 0.f, 0.f);

    float4 pf[16];
    {
        const int base = bx * TILE;
        const int valid = (NNODES - base < TILE) ? (NNODES - base) : TILE;
        #pragma unroll
        for (int j = 0; j < 16; j++) {
            int i = tid + j * NTHR;
            int n = i >> 6, c4 = (i & 63) << 2;
            pf[j] = (n < valid) ? *(const float4*)(x + (size_t)(base + n) * CIN + c4)
                                : make_float4(0.f, 0.f, 0.f, 0.f);
        }
    }
    __syncthreads();

    for (int tile = bx; tile < NT; tile += BPH) {
        // ---- store prefetched tile (both copies) + colsum partials
        #pragma unroll
        for (int j = 0; j < 16; j++) {
            int i = tid + j * NTHR;
            int n = i >> 6, c4 = (i & 63) << 2;
            float4 v = pf[j];
            csacc.x += v.x; csacc.y += v.y; csacc.z += v.z; csacc.w += v.w;
            float4 r = make_float4(rna(v.x), rna(v.y), rna(v.z), rna(v.w));
            *(float4*)(xsA + n * XS + c4) = r;
            *(float4*)(xsB + n * 256 + (c4 ^ (8 * (n & 3)))) = r;
        }
        __syncthreads();

        // ---- prefetch next tile
        if (tile + BPH < NT) {
            const int nb = (tile + BPH) * TILE;
            const int nv = (NNODES - nb < TILE) ? (NNODES - nb) : TILE;
            #pragma unroll
            for (int j = 0; j < 16; j++) {
                int i = tid + j * NTHR;
                int n = i >> 6, c4 = (i & 63) << 2;
                pf[j] = (n < nv) ? *(const float4*)(x + (size_t)(nb + n) * CIN + c4)
                                 : make_float4(0.f, 0.f, 0.f, 0.f);
            }
        }

        const int base = tile * TILE;
        const int valid = (NNODES - base < TILE) ? (NNODES - base) : TILE;

        // ---- k projection (16x32 per warp) + fused row-norm partials
        {
            float pc[4][4];
            #pragma unroll
            for (int t = 0; t < 4; t++) { pc[t][0]=0.f; pc[t][1]=0.f; pc[t][2]=0.f; pc[t][3]=0.f; }
            #pragma unroll 4
            for (int kb = 0; kb < 32; kb++) {
                const float* xr = xsA + (ps * 16 + gq) * XS + kb * 8 + ct;
                uint4 a;
                a.x = fu(xr[0]); a.y = fu(xr[8 * XS]);
                a.z = fu(xr[4]); a.w = fu(xr[8 * XS + 4]);
                #pragma unroll
                for (int t = 0; t < 4; t++) {
                    int nt = nh * 4 + t;
                    const float* wp = wt + (kb * 8 + ct) * 64 + ((nt * 8 + gq) ^ (8 * ct));
                    uint2 b; b.x = fu(wp[0]); b.y = fu(wp[4 * 64]);
                    mma8(pc[t], a, b);
                }
            }
            int r0 = ps * 16 + gq;
            float nrm0 = 0.f, nrm1 = 0.f;
            #pragma unroll
            for (int t = 0; t < 4; t++) {
                int cb = (nh * 4 + t) * 8 + 2 * ct;
                float b0 = bias[cb], b1 = bias[cb + 1];
                float v0 = pc[t][0] + b0, v1 = pc[t][1] + b1;
                float v2 = pc[t][2] + b0, v3 = pc[t][3] + b1;
                *(float2*)(ks + r0 * KS + cb)       = make_float2(v0, v1);
                *(float2*)(ks + (r0 + 8) * KS + cb) = make_float2(v2, v3);
                nrm0 += v0 * v0 + v1 * v1;
                nrm1 += v2 * v2 + v3 * v3;
            }
            nrm0 += __shfl_xor_sync(0xffffffffu, nrm0, 1);
            nrm0 += __shfl_xor_sync(0xffffffffu, nrm0, 2);
            nrm1 += __shfl_xor_sync(0xffffffffu, nrm1, 1);
            nrm1 += __shfl_xor_sync(0xffffffffu, nrm1, 2);
            if (ct == 0) {
                red[r0 * 2 + nh]       = nrm0;
                red[(r0 + 8) * 2 + nh] = nrm1;
            }
        }
        __syncthreads();

        if (tid < 64) {
            float s = red[tid * 2] + red[tid * 2 + 1];
            inv[tid] = (tid < valid) ? rsqrtf(s) : 0.f;
        }
        __syncthreads();

        // ---- merged normalize + ks_sum partials (single pass over ks)
        {
            int m = tid & 63, rg = tid >> 6;
            float s = 0.f;
            #pragma unroll
            for (int r = 0; r < 16; r++) {
                int n = rg * 16 + r;
                float v = rna(ks[n * KS + m] * inv[n]);
                ks[n * KS + m] = v;
                s += v;
            }
            red[rg * 64 + m] = s;
        }
        __syncthreads();
        if (tid < 64)
            kss[tid] += red[tid] + red[64 + tid] + red[128 + tid] + red[192 + tid];

        // ---- kv += ks^T @ x   (32x64 per warp; b reused across 2 m-frags)
        {
            #pragma unroll
            for (int kb = 0; kb < 8; kb++) {
                uint4 a0, a1;
                {
                    const float* kp = ks + (kb * 8 + ct) * KS + km * 32 + gq;
                    a0.x = fu(kp[0]);      a0.y = fu(kp[8]);
                    a0.z = fu(kp[4 * KS]); a0.w = fu(kp[4 * KS + 8]);
                    a1.x = fu(kp[16]);     a1.y = fu(kp[24]);
                    a1.z = fu(kp[4 * KS + 16]); a1.w = fu(kp[4 * KS + 24]);
                }
                const float* xb0 = xsB + (kb * 8 + ct) * 256;
                const float* xb1 = xsB + (kb * 8 + ct + 4) * 256;
                const int sw = 8 * ct;
                #pragma unroll
                for (int t = 0; t < 8; t++) {
                    int c = cq * 64 + t * 8 + gq;
                    uint2 b; b.x = fu(xb0[c ^ sw]); b.y = fu(xb1[c ^ sw]);
                    mma8(kvC[0][t], a0, b);
                    mma8(kvC[1][t], a1, b);
                }
            }
        }
        __syncthreads();
    }

    // ---- deterministic per-block partials
    {
        float* dst = g_part_kvs[bx] + h * (DHEAD * CIN);
        #pragma unroll
        for (int mi = 0; mi < 2; mi++)
            #pragma unroll
            for (int t = 0; t < 8; t++) {
                int c0 = cq * 64 + t * 8 + 2 * ct;
                int m0 = km * 32 + mi * 16 + gq;
                dst[m0 * 256 + c0]           = kvC[mi][t][0];
                dst[m0 * 256 + c0 + 1]       = kvC[mi][t][1];
                dst[(m0 + 8) * 256 + c0]     = kvC[mi][t][2];
                dst[(m0 + 8) * 256 + c0 + 1] = kvC[mi][t][3];
            }
    }
    if (tid < 64) g_part_kss[bx][h * 64 + tid] = kss[tid];
    {
        int c4 = (tid & 63) * 4, grp = tid >> 6;
        csred[(c4+0)*4+grp] = csacc.x; csred[(c4+1)*4+grp] = csacc.y;
        csred[(c4+2)*4+grp] = csacc.z; csred[(c4+3)*4+grp] = csacc.w;
    }
    __syncthreads();
    if (h == 0)
        g_part_cs[bx][tid] = csred[tid*4] + csred[tid*4+1] + csred[tid*4+2] + csred[tid*4+3];
}

// =====================================================================
// Reduce
// =====================================================================
__global__ void reduce_kernel()
{
    int i = blockIdx.x * 256 + threadIdx.x;
    if (i < NHEADS * DHEAD * CIN) {
        float s = 0.f;
        #pragma unroll 1
        for (int b = 0; b < BPH; b++) s += g_part_kvs[b][i];
        g_kvs[i] = s;
    }
    if (i < NHEADS * DHEAD) {
        float s = 0.f;
        for (int b = 0; b < BPH; b++) s += g_part_kss[b][i];
        g_kssum[i] = s;
    }
    if (i < CIN) {
        float s = 0.f;
        for (int b = 0; b < BPH; b++) s += g_part_cs[b][i];
        g_colsum[i] = s;
    }
}

// =====================================================================
// Phase B  (256 threads; proj 16x32, out-GEMM 32x64 per warp)
// smem floats: xsA 16640 | wt 16384 | kvs 16384 | qs 4352 | bias 64 |
//   kss 64 | cs 256 | red 128 | red2 128 | inv 64 | rno 64 = 54528 (218112 B)
// =====================================================================
__global__ __launch_bounds__(NTHR, 1)
void phaseB_kernel(const float* __restrict__ x,
                   const float* __restrict__ Wq,
                   const float* __restrict__ bq,
                   float* __restrict__ out)
{
    const int h = blockIdx.y, tid = threadIdx.x;
    const int lane = tid & 31, w = tid >> 5;
    const int gq = lane >> 2, ct = lane & 3;

    float* xsA  = smf;             // [64][260]
    float* wt   = xsA + 16640;     // [256][64] swizzled
    float* kvs  = wt  + 16384;     // [64][256] swizzled: phys_c = c ^ (8*(m&3))
    float* qs   = kvs + 16384;     // [64][QS]
    float* bias = qs  + 4352;
    float* kss  = bias + 64;
    float* cs   = kss + 64;
    float* red  = cs  + 256;       // [128]
    float* red2 = red + 128;       // [128]
    float* inv  = red2 + 128;      // [64]
    float* rno  = inv + 64;        // [64]

    for (int i = tid; i < 16384; i += NTHR) {
        int c = i >> 6, m = i & 63;
        wt[c * 64 + (m ^ (8 * (c & 3)))] = rna(Wq[(h * 64 + m) * 256 + c]);
    }
    for (int i = tid; i < 16384; i += NTHR) {
        int m = i >> 8, c = i & 255;
        kvs[m * 256 + (c ^ (8 * (m & 3)))] = rna(g_kvs[h * 16384 + m * 256 + c]);
    }
    if (tid < 64) { bias[tid] = bq[h * 64 + tid]; kss[tid] = g_kssum[h * 64 + tid]; }
    cs[tid] = g_colsum[tid];

    const int ps = w >> 1, nh = w & 1;   // proj
    const int sn = w >> 2, cq = w & 3;   // out: 2 row-slabs(32) x 4 c-quarters(64)

    float4 pf[16];
    {
        const int base = blockIdx.x * TILE;
        const int valid = (NNODES - base < TILE) ? (NNODES - base) : TILE;
        #pragma unroll
        for (int j = 0; j < 16; j++) {
            int i = tid + j * NTHR;
            int n = i >> 6, c4 = (i & 63) << 2;
            pf[j] = (n < valid) ? *(const float4*)(x + (size_t)(base + n) * CIN + c4)
                                : make_float4(0.f, 0.f, 0.f, 0.f);
        }
    }
    __syncthreads();

    for (int tile = blockIdx.x; tile < NT; tile += BPH) {
        #pragma unroll
        for (int j = 0; j < 16; j++) {
            int i = tid + j * NTHR;
            int n = i >> 6, c4 = (i & 63) << 2;
            float4 v = pf[j];
            *(float4*)(xsA + n * XS + c4) =
                make_float4(rna(v.x), rna(v.y), rna(v.z), rna(v.w));
        }
        __syncthreads();

        if (tile + BPH < NT) {
            const int nb = (tile + BPH) * TILE;
            const int nv = (NNODES - nb < TILE) ? (NNODES - nb) : TILE;
            #pragma unroll
            for (int j = 0; j < 16; j++) {
                int i = tid + j * NTHR;
                int n = i >> 6, c4 = (i & 63) << 2;
                pf[j] = (n < nv) ? *(const float4*)(x + (size_t)(nb + n) * CIN + c4)
                                 : make_float4(0.f, 0.f, 0.f, 0.f);
            }
        }

        const int base = tile * TILE;
        const int valid = (NNODES - base < TILE) ? (NNODES - base) : TILE;

        // ---- q projection + fused row-norm & ks_sum-dot partials
        {
            float pc[4][4];
            #pragma unroll
            for (int t = 0; t < 4; t++) { pc[t][0]=0.f; pc[t][1]=0.f; pc[t][2]=0.f; pc[t][3]=0.f; }
            #pragma unroll 4
            for (int kb = 0; kb < 32; kb++) {
                const float* xr = xsA + (ps * 16 + gq) * XS + kb * 8 + ct;
                uint4 a;
                a.x = fu(xr[0]); a.y = fu(xr[8 * XS]);
                a.z = fu(xr[4]); a.w = fu(xr[8 * XS + 4]);
                #pragma unroll
                for (int t = 0; t < 4; t++) {
                    int nt = nh * 4 + t;
                    const float* wp = wt + (kb * 8 + ct) * 64 + ((nt * 8 + gq) ^ (8 * ct));
                    uint2 b; b.x = fu(wp[0]); b.y = fu(wp[4 * 64]);
                    mma8(pc[t], a, b);
                }
            }
            int r0 = ps * 16 + gq;
            float nrm0 = 0.f, nrm1 = 0.f, dot0 = 0.f, dot1 = 0.f;
            #pragma unroll
            for (int t = 0; t < 4; t++) {
                int cb = (nh * 4 + t) * 8 + 2 * ct;
                float b0 = bias[cb], b1 = bias[cb + 1];
                float k0 = kss[cb],  k1 = kss[cb + 1];
                float v0 = pc[t][0] + b0, v1 = pc[t][1] + b1;
                float v2 = pc[t][2] + b0, v3 = pc[t][3] + b1;
                *(float2*)(qs + r0 * QS + cb)       = make_float2(v0, v1);
                *(float2*)(qs + (r0 + 8) * QS + cb) = make_float2(v2, v3);
                nrm0 += v0 * v0 + v1 * v1;  dot0 += v0 * k0 + v1 * k1;
                nrm1 += v2 * v2 + v3 * v3;  dot1 += v2 * k0 + v3 * k1;
            }
            nrm0 += __shfl_xor_sync(0xffffffffu, nrm0, 1);
            nrm0 += __shfl_xor_sync(0xffffffffu, nrm0, 2);
            nrm1 += __shfl_xor_sync(0xffffffffu, nrm1, 1);
            nrm1 += __shfl_xor_sync(0xffffffffu, nrm1, 2);
            dot0 += __shfl_xor_sync(0xffffffffu, dot0, 1);
            dot0 += __shfl_xor_sync(0xffffffffu, dot0, 2);
            dot1 += __shfl_xor_sync(0xffffffffu, dot1, 1);
            dot1 += __shfl_xor_sync(0xffffffffu, dot1, 2);
            if (ct == 0) {
                red [r0 * 2 + nh] = nrm0;  red [(r0 + 8) * 2 + nh] = nrm1;
                red2[r0 * 2 + nh] = dot0;  red2[(r0 + 8) * 2 + nh] = dot1;
            }
        }
        __syncthreads();

        if (tid < 64) {
            float s = red [tid * 2] + red [tid * 2 + 1];
            float d = red2[tid * 2] + red2[tid * 2 + 1];
            float iv = rsqrtf(s);
            inv[tid] = iv;
            rno[tid] = 1.0f / (iv * d + (float)NNODES);
        }
        __syncthreads();
        {
            int m = tid & 63, rg = tid >> 6;
            #pragma unroll
            for (int r = 0; r < 16; r++) {
                int n = rg * 16 + r;
                qs[n * QS + m] = rna(qs[n * QS + m] * inv[n]);
            }
        }
        __syncthreads();

        // ---- out = (qs @ kvs + colsum) * rno   (32x64 per warp)
        {
            float oc[2][8][4];
            #pragma unroll
            for (int mi = 0; mi < 2; mi++)
                #pragma unroll
                for (int t = 0; t < 8; t++) {
                    oc[mi][t][0]=0.f; oc[mi][t][1]=0.f; oc[mi][t][2]=0.f; oc[mi][t][3]=0.f;
                }
            #pragma unroll
            for (int kb = 0; kb < 8; kb++) {
                uint4 a0, a1;
                {
                    const float* ap = qs + (sn * 32 + gq) * QS + kb * 8 + ct;
                    a0.x = fu(ap[0]); a0.y = fu(ap[8 * QS]);
                    a0.z = fu(ap[4]); a0.w = fu(ap[8 * QS + 4]);
                    const float* ap1 = ap + 16 * QS;
                    a1.x = fu(ap1[0]); a1.y = fu(ap1[8 * QS]);
                    a1.z = fu(ap1[4]); a1.w = fu(ap1[8 * QS + 4]);
                }
                const float* kp0 = kvs + (kb * 8 + ct) * 256;
                const float* kp1 = kvs + (kb * 8 + ct + 4) * 256;
                const int sw = 8 * ct;
                #pragma unroll
                for (int t = 0; t < 8; t++) {
                    int c = cq * 64 + t * 8 + gq;
                    uint2 b; b.x = fu(kp0[c ^ sw]); b.y = fu(kp1[c ^ sw]);
                    mma8(oc[0][t], a0, b);
                    mma8(oc[1][t], a1, b);
                }
            }
            #pragma unroll
            for (int mi = 0; mi < 2; mi++) {
                int n0 = sn * 32 + mi * 16 + gq;
                float r0v = rno[n0], r1v = rno[n0 + 8];
                #pragma unroll
                for (int t = 0; t < 8; t++) {
                    int c0 = cq * 64 + t * 8 + 2 * ct;
                    float cv0 = cs[c0], cv1 = cs[c0 + 1];
                    if (n0 < valid)
                        *(float2*)(out + (size_t)(base + n0) * (NHEADS * CIN) + h * CIN + c0) =
                            make_float2((oc[mi][t][0] + cv0) * r0v, (oc[mi][t][1] + cv1) * r0v);
                    if (n0 + 8 < valid)
                        *(float2*)(out + (size_t)(base + n0 + 8) * (NHEADS * CIN) + h * CIN + c0) =
                            make_float2((oc[mi][t][2] + cv0) * r1v, (oc[mi][t][3] + cv1) * r1v);
                }
            }
        }
        __syncthreads();
    }
}

// =====================================================================
extern "C" void kernel_launch(void* const* d_in, const int* in_sizes, int n_in,
                              void* d_out, int out_size)
{
    const float* x    = (const float*)d_in[0];
    const float* Wq_w = (const float*)d_in[1];
    const float* Wq_b = (const float*)d_in[2];
    const float* Wk_w = (const float*)d_in[3];
    const float* Wk_b = (const float*)d_in[4];
    float* out = (float*)d_out;

    const int smemA = 55744 * (int)sizeof(float);   // 222976 B
    const int smemB = 54528 * (int)sizeof(float);   // 218112 B

    cudaFuncSetAttribute(phaseA_kernel, cudaFuncAttributeMaxDynamicSharedMemorySize, smemA);
    cudaFuncSetAttribute(phaseB_kernel, cudaFuncAttributeMaxDynamicSharedMemorySize, smemB);

    phaseA_kernel<<<dim3(BPH, NHEADS), NTHR, smemA>>>(x, Wk_w, Wk_b);
    reduce_kernel<<<256, 256>>>();
    phaseB_kernel<<<dim3(BPH, NHEADS), NTHR, smemB>>>(x, Wq_w, Wq_b, out);
}